// round 6
// baseline (speedup 1.0000x reference)
#include <cuda_runtime.h>
#include <cuda_bf16.h>
#include <cstdint>

#define D_MODEL 1024
#define N_HEADS 16
#define DEPTH   64
#define BATCH   2
#define SEQ     2048
#define ROWS    (BATCH*SEQ)

// ---------------- scratch (device globals; no allocations) ----------------
__device__ float g_Q [ROWS * D_MODEL];
__device__ float g_K [ROWS * D_MODEL];
__device__ float g_V [ROWS * D_MODEL];
__device__ float g_AO[ROWS * D_MODEL];
__device__ __nv_bfloat16 g_inh[ROWS * D_MODEL];
__device__ __nv_bfloat16 g_inl[ROWS * D_MODEL];
__device__ __nv_bfloat16 g_wh [D_MODEL * D_MODEL];
__device__ __nv_bfloat16 g_wl [D_MODEL * D_MODEL];

// ---------------------------------------------------------------------------
// mma.sync helper: D += A(16x16 bf16) @ B(16x8 bf16), fp32 accum
// ---------------------------------------------------------------------------
__device__ __forceinline__ void mma16816(float* d, const uint32_t* a,
                                         uint32_t b0, uint32_t b1) {
    asm volatile(
        "mma.sync.aligned.m16n8k16.row.col.f32.bf16.bf16.f32 "
        "{%0,%1,%2,%3}, {%4,%5,%6,%7}, {%8,%9}, {%0,%1,%2,%3};"
        : "+f"(d[0]), "+f"(d[1]), "+f"(d[2]), "+f"(d[3])
        : "r"(a[0]), "r"(a[1]), "r"(a[2]), "r"(a[3]), "r"(b0), "r"(b1));
}

// ---------------------------------------------------------------------------
// Split fp32 -> (bf16 hi, bf16 lo)
// ---------------------------------------------------------------------------
__global__ __launch_bounds__(256) void split_kernel(
    const float* __restrict__ in, __nv_bfloat16* __restrict__ hi,
    __nv_bfloat16* __restrict__ lo, int n)
{
    int i = (blockIdx.x * 256 + threadIdx.x) * 4;
    if (i >= n) return;
    float4 v = *(const float4*)(in + i);
    union { __nv_bfloat16 b[4]; uint2 u; } H, L;
    float f[4] = {v.x, v.y, v.z, v.w};
    #pragma unroll
    for (int j = 0; j < 4; j++) {
        H.b[j] = __float2bfloat16_rn(f[j]);
        L.b[j] = __float2bfloat16_rn(f[j] - __bfloat162float(H.b[j]));
    }
    *(uint2*)(hi + i) = H.u;
    *(uint2*)(lo + i) = L.u;
}

// ---------------------------------------------------------------------------
// Transpose + split: W[K][N] fp32 -> Wt_hi/Wt_lo[N][K] bf16
// ---------------------------------------------------------------------------
__global__ __launch_bounds__(256) void split_t_kernel(
    const float* __restrict__ W, __nv_bfloat16* __restrict__ th,
    __nv_bfloat16* __restrict__ tl)
{
    __shared__ float tile[32][33];
    int x  = blockIdx.x * 32 + threadIdx.x;   // N index
    int y0 = blockIdx.y * 32;                 // K index
    #pragma unroll
    for (int i = 0; i < 32; i += 8)
        tile[threadIdx.y + i][threadIdx.x] = W[(size_t)(y0 + threadIdx.y + i) * D_MODEL + x];
    __syncthreads();
    int k = y0 + threadIdx.x;
    #pragma unroll
    for (int i = 0; i < 32; i += 8) {
        int nn = blockIdx.x * 32 + threadIdx.y + i;
        float v = tile[threadIdx.x][threadIdx.y + i];
        __nv_bfloat16 h = __float2bfloat16_rn(v);
        th[(size_t)nn * D_MODEL + k] = h;
        tl[(size_t)nn * D_MODEL + k] = __float2bfloat16_rn(v - __bfloat162float(h));
    }
}

// ---------------------------------------------------------------------------
// bf16x2-split GEMM via mma.sync: C[M,N] = A @ W + bias
//   Ah/Al: [M,K] bf16 row-major.  Bh/Bl: [N,K] bf16 row-major (i.e. W^T).
// CTA tile 128x128, 8 warps (warp tile 32m x 64n), BK=32.
// D = AhBh + AhBl + AlBh  (fp32 accum).
// ---------------------------------------------------------------------------
#define SA 40   // smem row stride in bf16 (80 B) -> conflict-free frag loads

__global__ __launch_bounds__(256, 2) void gemm_mma(
    const __nv_bfloat16* __restrict__ Ah, const __nv_bfloat16* __restrict__ Al,
    const __nv_bfloat16* __restrict__ Bh, const __nv_bfloat16* __restrict__ Bl,
    const float* __restrict__ bias, float* __restrict__ C)
{
    __shared__ __nv_bfloat16 sAh[128 * SA], sAl[128 * SA];
    __shared__ __nv_bfloat16 sBh[128 * SA], sBl[128 * SA];

    const int tid  = threadIdx.x;
    const int wid  = tid >> 5, lane = tid & 31;
    const int wm   = wid & 3;          // 0..3 -> m rows wm*32
    const int wn   = wid >> 2;         // 0..1 -> n cols wn*64
    const int m0   = blockIdx.y * 128, n0 = blockIdx.x * 128;
    const int lg   = lane >> 2;        // 0..7
    const int lk   = (lane & 3) * 2;   // 0,2,4,6

    float acc[2][8][4];
    #pragma unroll
    for (int mt = 0; mt < 2; mt++)
        #pragma unroll
        for (int nt = 0; nt < 8; nt++)
            #pragma unroll
            for (int r = 0; r < 4; r++) acc[mt][nt][r] = 0.f;

    for (int k0 = 0; k0 < D_MODEL; k0 += 32) {
        __syncthreads();
        // 128 rows x 32 cols per tile; thread loads 2 x uint4 (8 bf16) per tile
        #pragma unroll
        for (int i = 0; i < 2; i++) {
            int idx = tid + i * 256;       // 0..511
            int r = idx >> 2, c = (idx & 3) * 8;
            size_t ga = (size_t)(m0 + r) * D_MODEL + k0 + c;
            size_t gb = (size_t)(n0 + r) * D_MODEL + k0 + c;
            *(uint4*)&sAh[r * SA + c] = *(const uint4*)(Ah + ga);
            *(uint4*)&sAl[r * SA + c] = *(const uint4*)(Al + ga);
            *(uint4*)&sBh[r * SA + c] = *(const uint4*)(Bh + gb);
            *(uint4*)&sBl[r * SA + c] = *(const uint4*)(Bl + gb);
        }
        __syncthreads();

        #pragma unroll
        for (int kk = 0; kk < 32; kk += 16) {
            uint32_t ah[2][4], al[2][4];
            #pragma unroll
            for (int mt = 0; mt < 2; mt++) {
                int row = wm * 32 + mt * 16 + lg;
                int base = row * SA + kk + lk;
                ah[mt][0] = *(const uint32_t*)&sAh[base];
                ah[mt][1] = *(const uint32_t*)&sAh[base + 8 * SA];
                ah[mt][2] = *(const uint32_t*)&sAh[base + 8];
                ah[mt][3] = *(const uint32_t*)&sAh[base + 8 * SA + 8];
                al[mt][0] = *(const uint32_t*)&sAl[base];
                al[mt][1] = *(const uint32_t*)&sAl[base + 8 * SA];
                al[mt][2] = *(const uint32_t*)&sAl[base + 8];
                al[mt][3] = *(const uint32_t*)&sAl[base + 8 * SA + 8];
            }
            #pragma unroll
            for (int nt = 0; nt < 8; nt++) {
                int nrow = wn * 64 + nt * 8 + lg;
                int base = nrow * SA + kk + lk;
                uint32_t bh0 = *(const uint32_t*)&sBh[base];
                uint32_t bh1 = *(const uint32_t*)&sBh[base + 8];
                uint32_t bl0 = *(const uint32_t*)&sBl[base];
                uint32_t bl1 = *(const uint32_t*)&sBl[base + 8];
                #pragma unroll
                for (int mt = 0; mt < 2; mt++) {
                    mma16816(acc[mt][nt], ah[mt], bh0, bh1);
                    mma16816(acc[mt][nt], ah[mt], bl0, bl1);
                    mma16816(acc[mt][nt], al[mt], bh0, bh1);
                }
            }
        }
    }

    // Epilogue: c0,c1 at (row=lg, col=lk..lk+1), c2,c3 at row lg+8
    #pragma unroll
    for (int mt = 0; mt < 2; mt++) {
        #pragma unroll
        for (int nt = 0; nt < 8; nt++) {
            int row = m0 + wm * 32 + mt * 16 + lg;
            int col = n0 + wn * 64 + nt * 8 + lk;
            float2 bb = *(const float2*)&bias[col];
            float2 o0, o1;
            o0.x = acc[mt][nt][0] + bb.x; o0.y = acc[mt][nt][1] + bb.y;
            o1.x = acc[mt][nt][2] + bb.x; o1.y = acc[mt][nt][3] + bb.y;
            *(float2*)&C[(size_t)row * D_MODEL + col] = o0;
            *(float2*)&C[(size_t)(row + 8) * D_MODEL + col] = o1;
        }
    }
}

// ---------------------------------------------------------------------------
// Flash-attention (fp32, causal, UNSCALED scores) — unchanged from R1.
// ---------------------------------------------------------------------------
#define SP 65

__global__ __launch_bounds__(256) void attn_kernel(
    const float* __restrict__ Qg, const float* __restrict__ Kg,
    const float* __restrict__ Vg, float* __restrict__ Og)
{
    extern __shared__ float sm[];
    float* Qs = sm;
    float* Ks = Qs + 64 * SP;
    float* Vs = Ks + 64 * SP;
    float* Ps = Vs + 64 * SP;

    const int qt = blockIdx.x;
    const int h  = blockIdx.y;
    const int b  = blockIdx.z;
    const int tid = threadIdx.x;
    const int ty = tid >> 4;
    const int tx = tid & 15;

    const size_t base = ((size_t)b * SEQ) * D_MODEL + h * DEPTH;
    const int q0 = qt * 64;

    #pragma unroll
    for (int i = 0; i < 4; i++) {
        int idx = tid + i * 256;
        int row = idx >> 4;
        int c4  = (idx & 15) << 2;
        float4 v = *(const float4*)&Qg[base + (size_t)(q0 + row) * D_MODEL + c4];
        Qs[row * SP + c4 + 0] = v.x; Qs[row * SP + c4 + 1] = v.y;
        Qs[row * SP + c4 + 2] = v.z; Qs[row * SP + c4 + 3] = v.w;
    }

    float m[4], l[4], acc[4][4];
    #pragma unroll
    for (int i = 0; i < 4; i++) {
        m[i] = -1e30f; l[i] = 0.f;
        #pragma unroll
        for (int j = 0; j < 4; j++) acc[i][j] = 0.f;
    }

    for (int kt = 0; kt <= qt; kt++) {
        __syncthreads();
        const int k0 = kt * 64;
        #pragma unroll
        for (int i = 0; i < 4; i++) {
            int idx = tid + i * 256;
            int row = idx >> 4;
            int c4  = (idx & 15) << 2;
            float4 kv = *(const float4*)&Kg[base + (size_t)(k0 + row) * D_MODEL + c4];
            float4 vv = *(const float4*)&Vg[base + (size_t)(k0 + row) * D_MODEL + c4];
            Ks[row * SP + c4 + 0] = kv.x; Ks[row * SP + c4 + 1] = kv.y;
            Ks[row * SP + c4 + 2] = kv.z; Ks[row * SP + c4 + 3] = kv.w;
            Vs[row * SP + c4 + 0] = vv.x; Vs[row * SP + c4 + 1] = vv.y;
            Vs[row * SP + c4 + 2] = vv.z; Vs[row * SP + c4 + 3] = vv.w;
        }
        __syncthreads();

        float s[4][4];
        #pragma unroll
        for (int i = 0; i < 4; i++)
            #pragma unroll
            for (int j = 0; j < 4; j++) s[i][j] = 0.f;

        #pragma unroll 8
        for (int d = 0; d < 64; d++) {
            float qr[4], kr[4];
            #pragma unroll
            for (int i = 0; i < 4; i++) qr[i] = Qs[(ty * 4 + i) * SP + d];
            #pragma unroll
            for (int j = 0; j < 4; j++) kr[j] = Ks[(tx * 4 + j) * SP + d];
            #pragma unroll
            for (int i = 0; i < 4; i++)
                #pragma unroll
                for (int j = 0; j < 4; j++)
                    s[i][j] = fmaf(qr[i], kr[j], s[i][j]);
        }

        if (kt == qt) {
            #pragma unroll
            for (int i = 0; i < 4; i++)
                #pragma unroll
                for (int j = 0; j < 4; j++)
                    if (tx * 4 + j > ty * 4 + i) s[i][j] = -1e30f;
        }

        #pragma unroll
        for (int i = 0; i < 4; i++) {
            float rm = fmaxf(fmaxf(s[i][0], s[i][1]), fmaxf(s[i][2], s[i][3]));
            #pragma unroll
            for (int off = 1; off < 16; off <<= 1)
                rm = fmaxf(rm, __shfl_xor_sync(0xffffffffu, rm, off));
            float mn = fmaxf(m[i], rm);
            float corr = __expf(m[i] - mn);
            m[i] = mn;
            float rs = 0.f;
            #pragma unroll
            for (int j = 0; j < 4; j++) {
                float p = __expf(s[i][j] - mn);
                s[i][j] = p;
                rs += p;
            }
            #pragma unroll
            for (int off = 1; off < 16; off <<= 1)
                rs += __shfl_xor_sync(0xffffffffu, rs, off);
            l[i] = l[i] * corr + rs;
            #pragma unroll
            for (int j = 0; j < 4; j++) {
                acc[i][j] *= corr;
                Ps[(ty * 4 + i) * SP + tx * 4 + j] = s[i][j];
            }
        }
        __syncthreads();

        #pragma unroll 8
        for (int c = 0; c < 64; c++) {
            float pr[4], vv[4];
            #pragma unroll
            for (int i = 0; i < 4; i++) pr[i] = Ps[(ty * 4 + i) * SP + c];
            #pragma unroll
            for (int j = 0; j < 4; j++) vv[j] = Vs[c * SP + tx * 4 + j];
            #pragma unroll
            for (int i = 0; i < 4; i++)
                #pragma unroll
                for (int j = 0; j < 4; j++)
                    acc[i][j] = fmaf(pr[i], vv[j], acc[i][j]);
        }
    }

    #pragma unroll
    for (int i = 0; i < 4; i++) {
        float inv = 1.f / l[i];
        float4 o;
        o.x = acc[i][0] * inv; o.y = acc[i][1] * inv;
        o.z = acc[i][2] * inv; o.w = acc[i][3] * inv;
        *(float4*)&Og[base + (size_t)(q0 + ty * 4 + i) * D_MODEL + tx * 4] = o;
    }
}

// ---------------------------------------------------------------------------
// Launch
// ---------------------------------------------------------------------------
extern "C" void kernel_launch(void* const* d_in, const int* in_sizes, int n_in,
                              void* d_out, int out_size)
{
    const float* q  = (const float*)d_in[0];
    const float* k  = (const float*)d_in[1];
    const float* v  = (const float*)d_in[2];
    const float* wq = (const float*)d_in[3];
    const float* bq = (const float*)d_in[4];
    const float* wk = (const float*)d_in[5];
    const float* bk = (const float*)d_in[6];
    const float* wv = (const float*)d_in[7];
    const float* bv = (const float*)d_in[8];
    const float* wo = (const float*)d_in[9];
    const float* bo = (const float*)d_in[10];
    float* out = (float*)d_out;

    float *Qb, *Kb, *Vb, *AOb;
    __nv_bfloat16 *inh, *inl, *wh, *wl;
    cudaGetSymbolAddress((void**)&Qb,  g_Q);
    cudaGetSymbolAddress((void**)&Kb,  g_K);
    cudaGetSymbolAddress((void**)&Vb,  g_V);
    cudaGetSymbolAddress((void**)&AOb, g_AO);
    cudaGetSymbolAddress((void**)&inh, g_inh);
    cudaGetSymbolAddress((void**)&inl, g_inl);
    cudaGetSymbolAddress((void**)&wh,  g_wh);
    cudaGetSymbolAddress((void**)&wl,  g_wl);

    const int asmem = 4 * 64 * SP * (int)sizeof(float);
    cudaFuncSetAttribute(attn_kernel,
                         cudaFuncAttributeMaxDynamicSharedMemorySize, asmem);

    const int nElems = ROWS * D_MODEL;
    dim3 sgrid(nElems / 4 / 256);
    dim3 tgrid(D_MODEL / 32, D_MODEL / 32), tblk(32, 8);
    dim3 ggrid(D_MODEL / 128, ROWS / 128);   // (8, 32)

    // Q projection
    split_t_kernel<<<tgrid, tblk>>>(wq, wh, wl);
    split_kernel<<<sgrid, 256>>>(q, inh, inl, nElems);
    gemm_mma<<<ggrid, 256>>>(inh, inl, wh, wl, bq, Qb);
    // K projection
    split_t_kernel<<<tgrid, tblk>>>(wk, wh, wl);
    split_kernel<<<sgrid, 256>>>(k, inh, inl, nElems);
    gemm_mma<<<ggrid, 256>>>(inh, inl, wh, wl, bk, Kb);
    // V projection
    split_t_kernel<<<tgrid, tblk>>>(wv, wh, wl);
    split_kernel<<<sgrid, 256>>>(v, inh, inl, nElems);
    gemm_mma<<<ggrid, 256>>>(inh, inl, wh, wl, bv, Vb);

    // attention
    dim3 agrid(SEQ / 64, N_HEADS, BATCH);
    attn_kernel<<<agrid, 256, asmem>>>(Qb, Kb, Vb, AOb);

    // output projection
    split_t_kernel<<<tgrid, tblk>>>(wo, wh, wl);
    split_kernel<<<sgrid, 256>>>(AOb, inh, inl, nElems);
    gemm_mma<<<ggrid, 256>>>(inh, inl, wh, wl, bo, out);
}

// round 7
// speedup vs baseline: 1.6720x; 1.6720x over previous
#include <cuda_runtime.h>
#include <cuda_bf16.h>
#include <cstdint>

#define D_MODEL 1024
#define N_HEADS 16
#define DEPTH   64
#define BATCH   2
#define SEQ     2048
#define ROWS    (BATCH*SEQ)

// ---------------- scratch (device globals; no allocations) ----------------
__device__ float g_Q [ROWS * D_MODEL];
__device__ float g_K [ROWS * D_MODEL];
__device__ float g_V [ROWS * D_MODEL];
__device__ float g_AO[ROWS * D_MODEL];
__device__ __nv_bfloat16 g_inh[ROWS * D_MODEL];
__device__ __nv_bfloat16 g_inl[ROWS * D_MODEL];
__device__ __nv_bfloat16 g_wh [D_MODEL * D_MODEL];
__device__ __nv_bfloat16 g_wl [D_MODEL * D_MODEL];

// ---------------- helpers ----------------
__device__ __forceinline__ uint32_t smem_u32(const void* p) {
    uint32_t a;
    asm("{ .reg .u64 t; cvta.to.shared.u64 t, %1; cvt.u32.u64 %0, t; }"
        : "=r"(a) : "l"(p));
    return a;
}
__device__ __forceinline__ void mma16816(float* d, const uint32_t* a,
                                         uint32_t b0, uint32_t b1) {
    asm volatile(
        "mma.sync.aligned.m16n8k16.row.col.f32.bf16.bf16.f32 "
        "{%0,%1,%2,%3}, {%4,%5,%6,%7}, {%8,%9}, {%0,%1,%2,%3};"
        : "+f"(d[0]), "+f"(d[1]), "+f"(d[2]), "+f"(d[3])
        : "r"(a[0]), "r"(a[1]), "r"(a[2]), "r"(a[3]), "r"(b0), "r"(b1));
}
#define LDMX4(r0, r1, r2, r3, addr) \
    asm volatile("ldmatrix.sync.aligned.m8n8.x4.shared.b16 {%0,%1,%2,%3}, [%4];" \
                 : "=r"(r0), "=r"(r1), "=r"(r2), "=r"(r3) : "r"(addr))
#define CPASYNC16(smaddr, gptr) \
    asm volatile("cp.async.cg.shared.global [%0], [%1], 16;" \
                 :: "r"(smaddr), "l"(gptr) : "memory")
#define CPCOMMIT()  asm volatile("cp.async.commit_group;" ::: "memory")
#define CPWAIT(n)   asm volatile("cp.async.wait_group %0;" :: "n"(n) : "memory")

// ---------------------------------------------------------------------------
// Split fp32 -> (bf16 hi, bf16 lo)
// ---------------------------------------------------------------------------
__global__ __launch_bounds__(256) void split_kernel(
    const float* __restrict__ in, __nv_bfloat16* __restrict__ hi,
    __nv_bfloat16* __restrict__ lo, int n)
{
    int i = (blockIdx.x * 256 + threadIdx.x) * 4;
    if (i >= n) return;
    float4 v = *(const float4*)(in + i);
    union { __nv_bfloat16 b[4]; uint2 u; } H, L;
    float f[4] = {v.x, v.y, v.z, v.w};
    #pragma unroll
    for (int j = 0; j < 4; j++) {
        H.b[j] = __float2bfloat16_rn(f[j]);
        L.b[j] = __float2bfloat16_rn(f[j] - __bfloat162float(H.b[j]));
    }
    *(uint2*)(hi + i) = H.u;
    *(uint2*)(lo + i) = L.u;
}

// ---------------------------------------------------------------------------
// Transpose + split: W[K][N] fp32 -> Wt_hi/Wt_lo[N][K] bf16
// ---------------------------------------------------------------------------
__global__ __launch_bounds__(256) void split_t_kernel(
    const float* __restrict__ W, __nv_bfloat16* __restrict__ th,
    __nv_bfloat16* __restrict__ tl)
{
    __shared__ float tile[32][33];
    int x  = blockIdx.x * 32 + threadIdx.x;
    int y0 = blockIdx.y * 32;
    #pragma unroll
    for (int i = 0; i < 32; i += 8)
        tile[threadIdx.y + i][threadIdx.x] = W[(size_t)(y0 + threadIdx.y + i) * D_MODEL + x];
    __syncthreads();
    int k = y0 + threadIdx.x;
    #pragma unroll
    for (int i = 0; i < 32; i += 8) {
        int nn = blockIdx.x * 32 + threadIdx.y + i;
        float v = tile[threadIdx.x][threadIdx.y + i];
        __nv_bfloat16 h = __float2bfloat16_rn(v);
        th[(size_t)nn * D_MODEL + k] = h;
        tl[(size_t)nn * D_MODEL + k] = __float2bfloat16_rn(v - __bfloat162float(h));
    }
}

// ---------------------------------------------------------------------------
// bf16x2-split GEMM via mma.sync + ldmatrix + cp.async double buffering.
//   C[M,N] = A @ W + bias;  Ah/Al: [M,K] row-major, Bh/Bl: [N,K] row-major.
// CTA tile 128x128, 8 warps (32m x 64n each), BK=32, 2-stage pipeline.
// D = AhBh + AhBl + AlBh (fp32 accum).
// ---------------------------------------------------------------------------
#define SA 40                              // bf16 row stride (80 B)
#define MATB   (128 * SA * 2)              // 10240 B per matrix tile
#define STAGEB (4 * MATB)                  // 40960 B per stage
#define GSMEM  (2 * STAGEB)                // 81920 B total

__global__ __launch_bounds__(256, 2) void gemm_mma(
    const __nv_bfloat16* __restrict__ Ah, const __nv_bfloat16* __restrict__ Al,
    const __nv_bfloat16* __restrict__ Bh, const __nv_bfloat16* __restrict__ Bl,
    const float* __restrict__ bias, float* __restrict__ C)
{
    extern __shared__ char smem[];
    const uint32_t sb = smem_u32(smem);

    const int tid  = threadIdx.x;
    const int wid  = tid >> 5, lane = tid & 31;
    const int wm   = wid & 3;            // m warp row (0..3)
    const int wn   = wid >> 2;           // n warp col (0..1)
    const int m0   = blockIdx.y * 128, n0 = blockIdx.x * 128;
    const int lg   = lane >> 2;          // 0..7
    const int lk   = (lane & 3) * 2;     // 0,2,4,6

    // ldmatrix lane addressing components
    const int g8 = lane >> 3;            // 0..3 (matrix group)
    const int r8 = lane & 7;             // row within 8x8 matrix

    // loader indices: thread -> 2 chunks of 16B per matrix per stage
    const int ldr0 = tid >> 2;           // row for chunk 0 (0..63)... see loop
    const int ldc0 = (tid & 3);          // 16B column index

    float acc[2][8][4];
    #pragma unroll
    for (int mt = 0; mt < 2; mt++)
        #pragma unroll
        for (int nt = 0; nt < 8; nt++)
            #pragma unroll
            for (int r = 0; r < 4; r++) acc[mt][nt][r] = 0.f;

    // ---- async stage loader ----
    auto load_stage = [&](int st, int k0) {
        const uint32_t s = sb + st * STAGEB;
        #pragma unroll
        for (int i = 0; i < 2; i++) {
            int idx = tid + i * 256;         // 0..511
            int r   = idx >> 2;              // 0..127
            int c16 = idx & 3;               // 0..3 (16B chunks)
            uint32_t so = (uint32_t)(r * (SA * 2) + c16 * 16);
            size_t ga = (size_t)(m0 + r) * D_MODEL + k0 + c16 * 8;
            size_t gb = (size_t)(n0 + r) * D_MODEL + k0 + c16 * 8;
            CPASYNC16(s + 0 * MATB + so, Ah + ga);
            CPASYNC16(s + 1 * MATB + so, Al + ga);
            CPASYNC16(s + 2 * MATB + so, Bh + gb);
            CPASYNC16(s + 3 * MATB + so, Bl + gb);
        }
    };

    load_stage(0, 0);
    CPCOMMIT();

    const int NIT = D_MODEL / 32;   // 32
    for (int it = 0; it < NIT; it++) {
        if (it + 1 < NIT) {
            load_stage((it + 1) & 1, (it + 1) * 32);
            CPCOMMIT();
            CPWAIT(1);
        } else {
            CPWAIT(0);
        }
        __syncthreads();

        const uint32_t s   = sb + (it & 1) * STAGEB;
        const uint32_t sAh = s;
        const uint32_t sAl = s + MATB;
        const uint32_t sBh = s + 2 * MATB;
        const uint32_t sBl = s + 3 * MATB;

        #pragma unroll
        for (int kk = 0; kk < 32; kk += 16) {
            // A fragments (hi & lo) for both 16-row m-tiles
            uint32_t ah[2][4], al[2][4];
            #pragma unroll
            for (int mt = 0; mt < 2; mt++) {
                int row = wm * 32 + mt * 16 + (g8 & 1) * 8 + r8;
                int col = kk + (g8 >> 1) * 8;
                uint32_t off = (uint32_t)(row * (SA * 2) + col * 2);
                LDMX4(ah[mt][0], ah[mt][1], ah[mt][2], ah[mt][3], sAh + off);
                LDMX4(al[mt][0], al[mt][1], al[mt][2], al[mt][3], sAl + off);
            }
            // B fragment pairs: np covers nt = 2np, 2np+1
            #pragma unroll
            for (int np = 0; np < 4; np++) {
                int row = wn * 64 + np * 16 + (g8 >> 1) * 8 + r8;
                int col = kk + (g8 & 1) * 8;
                uint32_t off = (uint32_t)(row * (SA * 2) + col * 2);
                uint32_t bh0, bh1, bh2, bh3, bl0, bl1, bl2, bl3;
                LDMX4(bh0, bh1, bh2, bh3, sBh + off);
                LDMX4(bl0, bl1, bl2, bl3, sBl + off);
                #pragma unroll
                for (int mt = 0; mt < 2; mt++) {
                    mma16816(acc[mt][2 * np],     ah[mt], bh0, bh1);
                    mma16816(acc[mt][2 * np],     ah[mt], bl0, bl1);
                    mma16816(acc[mt][2 * np],     al[mt], bh0, bh1);
                    mma16816(acc[mt][2 * np + 1], ah[mt], bh2, bh3);
                    mma16816(acc[mt][2 * np + 1], ah[mt], bl2, bl3);
                    mma16816(acc[mt][2 * np + 1], al[mt], bh2, bh3);
                }
            }
        }
        __syncthreads();
    }

    // Epilogue: c0,c1 at (row=lg, col=lk), c2,c3 at row lg+8
    #pragma unroll
    for (int mt = 0; mt < 2; mt++) {
        #pragma unroll
        for (int nt = 0; nt < 8; nt++) {
            int row = m0 + wm * 32 + mt * 16 + lg;
            int col = n0 + wn * 64 + nt * 8 + lk;
            float2 bb = *(const float2*)&bias[col];
            float2 o0, o1;
            o0.x = acc[mt][nt][0] + bb.x; o0.y = acc[mt][nt][1] + bb.y;
            o1.x = acc[mt][nt][2] + bb.x; o1.y = acc[mt][nt][3] + bb.y;
            *(float2*)&C[(size_t)row * D_MODEL + col] = o0;
            *(float2*)&C[(size_t)(row + 8) * D_MODEL + col] = o1;
        }
    }
}

// ---------------------------------------------------------------------------
// Flash-attention (fp32, causal, UNSCALED scores) — unchanged (proven).
// ---------------------------------------------------------------------------
#define SP 65

__global__ __launch_bounds__(256) void attn_kernel(
    const float* __restrict__ Qg, const float* __restrict__ Kg,
    const float* __restrict__ Vg, float* __restrict__ Og)
{
    extern __shared__ float sm[];
    float* Qs = sm;
    float* Ks = Qs + 64 * SP;
    float* Vs = Ks + 64 * SP;
    float* Ps = Vs + 64 * SP;

    const int qt = blockIdx.x;
    const int h  = blockIdx.y;
    const int b  = blockIdx.z;
    const int tid = threadIdx.x;
    const int ty = tid >> 4;
    const int tx = tid & 15;

    const size_t base = ((size_t)b * SEQ) * D_MODEL + h * DEPTH;
    const int q0 = qt * 64;

    #pragma unroll
    for (int i = 0; i < 4; i++) {
        int idx = tid + i * 256;
        int row = idx >> 4;
        int c4  = (idx & 15) << 2;
        float4 v = *(const float4*)&Qg[base + (size_t)(q0 + row) * D_MODEL + c4];
        Qs[row * SP + c4 + 0] = v.x; Qs[row * SP + c4 + 1] = v.y;
        Qs[row * SP + c4 + 2] = v.z; Qs[row * SP + c4 + 3] = v.w;
    }

    float m[4], l[4], acc[4][4];
    #pragma unroll
    for (int i = 0; i < 4; i++) {
        m[i] = -1e30f; l[i] = 0.f;
        #pragma unroll
        for (int j = 0; j < 4; j++) acc[i][j] = 0.f;
    }

    for (int kt = 0; kt <= qt; kt++) {
        __syncthreads();
        const int k0 = kt * 64;
        #pragma unroll
        for (int i = 0; i < 4; i++) {
            int idx = tid + i * 256;
            int row = idx >> 4;
            int c4  = (idx & 15) << 2;
            float4 kv = *(const float4*)&Kg[base + (size_t)(k0 + row) * D_MODEL + c4];
            float4 vv = *(const float4*)&Vg[base + (size_t)(k0 + row) * D_MODEL + c4];
            Ks[row * SP + c4 + 0] = kv.x; Ks[row * SP + c4 + 1] = kv.y;
            Ks[row * SP + c4 + 2] = kv.z; Ks[row * SP + c4 + 3] = kv.w;
            Vs[row * SP + c4 + 0] = vv.x; Vs[row * SP + c4 + 1] = vv.y;
            Vs[row * SP + c4 + 2] = vv.z; Vs[row * SP + c4 + 3] = vv.w;
        }
        __syncthreads();

        float s[4][4];
        #pragma unroll
        for (int i = 0; i < 4; i++)
            #pragma unroll
            for (int j = 0; j < 4; j++) s[i][j] = 0.f;

        #pragma unroll 8
        for (int d = 0; d < 64; d++) {
            float qr[4], kr[4];
            #pragma unroll
            for (int i = 0; i < 4; i++) qr[i] = Qs[(ty * 4 + i) * SP + d];
            #pragma unroll
            for (int j = 0; j < 4; j++) kr[j] = Ks[(tx * 4 + j) * SP + d];
            #pragma unroll
            for (int i = 0; i < 4; i++)
                #pragma unroll
                for (int j = 0; j < 4; j++)
                    s[i][j] = fmaf(qr[i], kr[j], s[i][j]);
        }

        if (kt == qt) {
            #pragma unroll
            for (int i = 0; i < 4; i++)
                #pragma unroll
                for (int j = 0; j < 4; j++)
                    if (tx * 4 + j > ty * 4 + i) s[i][j] = -1e30f;
        }

        #pragma unroll
        for (int i = 0; i < 4; i++) {
            float rm = fmaxf(fmaxf(s[i][0], s[i][1]), fmaxf(s[i][2], s[i][3]));
            #pragma unroll
            for (int off = 1; off < 16; off <<= 1)
                rm = fmaxf(rm, __shfl_xor_sync(0xffffffffu, rm, off));
            float mn = fmaxf(m[i], rm);
            float corr = __expf(m[i] - mn);
            m[i] = mn;
            float rs = 0.f;
            #pragma unroll
            for (int j = 0; j < 4; j++) {
                float p = __expf(s[i][j] - mn);
                s[i][j] = p;
                rs += p;
            }
            #pragma unroll
            for (int off = 1; off < 16; off <<= 1)
                rs += __shfl_xor_sync(0xffffffffu, rs, off);
            l[i] = l[i] * corr + rs;
            #pragma unroll
            for (int j = 0; j < 4; j++) {
                acc[i][j] *= corr;
                Ps[(ty * 4 + i) * SP + tx * 4 + j] = s[i][j];
            }
        }
        __syncthreads();

        #pragma unroll 8
        for (int c = 0; c < 64; c++) {
            float pr[4], vv[4];
            #pragma unroll
            for (int i = 0; i < 4; i++) pr[i] = Ps[(ty * 4 + i) * SP + c];
            #pragma unroll
            for (int j = 0; j < 4; j++) vv[j] = Vs[c * SP + tx * 4 + j];
            #pragma unroll
            for (int i = 0; i < 4; i++)
                #pragma unroll
                for (int j = 0; j < 4; j++)
                    acc[i][j] = fmaf(pr[i], vv[j], acc[i][j]);
        }
    }

    #pragma unroll
    for (int i = 0; i < 4; i++) {
        float inv = 1.f / l[i];
        float4 o;
        o.x = acc[i][0] * inv; o.y = acc[i][1] * inv;
        o.z = acc[i][2] * inv; o.w = acc[i][3] * inv;
        *(float4*)&Og[base + (size_t)(q0 + ty * 4 + i) * D_MODEL + tx * 4] = o;
    }
}

// ---------------------------------------------------------------------------
// Launch
// ---------------------------------------------------------------------------
extern "C" void kernel_launch(void* const* d_in, const int* in_sizes, int n_in,
                              void* d_out, int out_size)
{
    const float* q  = (const float*)d_in[0];
    const float* k  = (const float*)d_in[1];
    const float* v  = (const float*)d_in[2];
    const float* wq = (const float*)d_in[3];
    const float* bq = (const float*)d_in[4];
    const float* wk = (const float*)d_in[5];
    const float* bk = (const float*)d_in[6];
    const float* wv = (const float*)d_in[7];
    const float* bv = (const float*)d_in[8];
    const float* wo = (const float*)d_in[9];
    const float* bo = (const float*)d_in[10];
    float* out = (float*)d_out;

    float *Qb, *Kb, *Vb, *AOb;
    __nv_bfloat16 *inh, *inl, *wh, *wl;
    cudaGetSymbolAddress((void**)&Qb,  g_Q);
    cudaGetSymbolAddress((void**)&Kb,  g_K);
    cudaGetSymbolAddress((void**)&Vb,  g_V);
    cudaGetSymbolAddress((void**)&AOb, g_AO);
    cudaGetSymbolAddress((void**)&inh, g_inh);
    cudaGetSymbolAddress((void**)&inl, g_inl);
    cudaGetSymbolAddress((void**)&wh,  g_wh);
    cudaGetSymbolAddress((void**)&wl,  g_wl);

    cudaFuncSetAttribute(gemm_mma,
                         cudaFuncAttributeMaxDynamicSharedMemorySize, GSMEM);
    const int asmem = 4 * 64 * SP * (int)sizeof(float);
    cudaFuncSetAttribute(attn_kernel,
                         cudaFuncAttributeMaxDynamicSharedMemorySize, asmem);

    const int nElems = ROWS * D_MODEL;
    dim3 sgrid(nElems / 4 / 256);
    dim3 tgrid(D_MODEL / 32, D_MODEL / 32), tblk(32, 8);
    dim3 ggrid(D_MODEL / 128, ROWS / 128);   // (8, 32)

    // Q projection
    split_t_kernel<<<tgrid, tblk>>>(wq, wh, wl);
    split_kernel<<<sgrid, 256>>>(q, inh, inl, nElems);
    gemm_mma<<<ggrid, 256, GSMEM>>>(inh, inl, wh, wl, bq, Qb);
    // K projection
    split_t_kernel<<<tgrid, tblk>>>(wk, wh, wl);
    split_kernel<<<sgrid, 256>>>(k, inh, inl, nElems);
    gemm_mma<<<ggrid, 256, GSMEM>>>(inh, inl, wh, wl, bk, Kb);
    // V projection
    split_t_kernel<<<tgrid, tblk>>>(wv, wh, wl);
    split_kernel<<<sgrid, 256>>>(v, inh, inl, nElems);
    gemm_mma<<<ggrid, 256, GSMEM>>>(inh, inl, wh, wl, bv, Vb);

    // attention
    dim3 agrid(SEQ / 64, N_HEADS, BATCH);
    attn_kernel<<<agrid, 256, asmem>>>(Qb, Kb, Vb, AOb);

    // output projection
    split_t_kernel<<<tgrid, tblk>>>(wo, wh, wl);
    split_kernel<<<sgrid, 256>>>(AOb, inh, inl, nElems);
    gemm_mma<<<ggrid, 256, GSMEM>>>(inh, inl, wh, wl, bo, out);
}

// round 9
// speedup vs baseline: 3.1932x; 1.9098x over previous
#include <cuda_runtime.h>
#include <cuda_bf16.h>
#include <cstdint>

#define D_MODEL 1024
#define N_HEADS 16
#define DEPTH   64
#define BATCH   2
#define SEQ     2048
#define ROWS    (BATCH*SEQ)

// ---------------- scratch (device globals; no allocations) ----------------
__device__ __nv_bfloat16 g_Qh [ROWS * D_MODEL];
__device__ __nv_bfloat16 g_Ql [ROWS * D_MODEL];
__device__ __nv_bfloat16 g_Kh [ROWS * D_MODEL];
__device__ __nv_bfloat16 g_Kl [ROWS * D_MODEL];
__device__ __nv_bfloat16 g_Vh [ROWS * D_MODEL];
__device__ __nv_bfloat16 g_Vl [ROWS * D_MODEL];
__device__ __nv_bfloat16 g_AOh[ROWS * D_MODEL];
__device__ __nv_bfloat16 g_AOl[ROWS * D_MODEL];
__device__ __nv_bfloat16 g_inh[ROWS * D_MODEL];
__device__ __nv_bfloat16 g_inl[ROWS * D_MODEL];
__device__ __nv_bfloat16 g_wh [D_MODEL * D_MODEL];
__device__ __nv_bfloat16 g_wl [D_MODEL * D_MODEL];

// ---------------- helpers ----------------
__device__ __forceinline__ uint32_t smem_u32(const void* p) {
    uint32_t a;
    asm("{ .reg .u64 t; cvta.to.shared.u64 t, %1; cvt.u32.u64 %0, t; }"
        : "=r"(a) : "l"(p));
    return a;
}
__device__ __forceinline__ void mma16816(float* d, const uint32_t* a,
                                         uint32_t b0, uint32_t b1) {
    asm volatile(
        "mma.sync.aligned.m16n8k16.row.col.f32.bf16.bf16.f32 "
        "{%0,%1,%2,%3}, {%4,%5,%6,%7}, {%8,%9}, {%0,%1,%2,%3};"
        : "+f"(d[0]), "+f"(d[1]), "+f"(d[2]), "+f"(d[3])
        : "r"(a[0]), "r"(a[1]), "r"(a[2]), "r"(a[3]), "r"(b0), "r"(b1));
}
#define LDMX4(r0, r1, r2, r3, addr) \
    asm volatile("ldmatrix.sync.aligned.m8n8.x4.shared.b16 {%0,%1,%2,%3}, [%4];" \
                 : "=r"(r0), "=r"(r1), "=r"(r2), "=r"(r3) : "r"(addr))
#define LDMX4T(r0, r1, r2, r3, addr) \
    asm volatile("ldmatrix.sync.aligned.m8n8.x4.trans.shared.b16 {%0,%1,%2,%3}, [%4];" \
                 : "=r"(r0), "=r"(r1), "=r"(r2), "=r"(r3) : "r"(addr))
#define CPASYNC16(smaddr, gptr) \
    asm volatile("cp.async.cg.shared.global [%0], [%1], 16;" \
                 :: "r"(smaddr), "l"(gptr) : "memory")
#define CPCOMMIT()  asm volatile("cp.async.commit_group;" ::: "memory")
#define CPWAIT(n)   asm volatile("cp.async.wait_group %0;" :: "n"(n) : "memory")

__device__ __forceinline__ uint32_t pack_bf16(float a, float b) {
    __nv_bfloat162 h = __floats2bfloat162_rn(a, b);
    return *(uint32_t*)&h;
}

// ---------------------------------------------------------------------------
// Split fp32 -> (bf16 hi, bf16 lo)
// ---------------------------------------------------------------------------
__global__ __launch_bounds__(256) void split_kernel(
    const float* __restrict__ in, __nv_bfloat16* __restrict__ hi,
    __nv_bfloat16* __restrict__ lo, int n)
{
    int i = (blockIdx.x * 256 + threadIdx.x) * 4;
    if (i >= n) return;
    float4 v = *(const float4*)(in + i);
    union { __nv_bfloat16 b[4]; uint2 u; } H, L;
    float f[4] = {v.x, v.y, v.z, v.w};
    #pragma unroll
    for (int j = 0; j < 4; j++) {
        H.b[j] = __float2bfloat16_rn(f[j]);
        L.b[j] = __float2bfloat16_rn(f[j] - __bfloat162float(H.b[j]));
    }
    *(uint2*)(hi + i) = H.u;
    *(uint2*)(lo + i) = L.u;
}

// ---------------------------------------------------------------------------
// Transpose + split: W[K][N] fp32 -> Wt_hi/Wt_lo[N][K] bf16
// ---------------------------------------------------------------------------
__global__ __launch_bounds__(256) void split_t_kernel(
    const float* __restrict__ W, __nv_bfloat16* __restrict__ th,
    __nv_bfloat16* __restrict__ tl)
{
    __shared__ float tile[32][33];
    int x  = blockIdx.x * 32 + threadIdx.x;
    int y0 = blockIdx.y * 32;
    #pragma unroll
    for (int i = 0; i < 32; i += 8)
        tile[threadIdx.y + i][threadIdx.x] = W[(size_t)(y0 + threadIdx.y + i) * D_MODEL + x];
    __syncthreads();
    int k = y0 + threadIdx.x;
    #pragma unroll
    for (int i = 0; i < 32; i += 8) {
        int nn = blockIdx.x * 32 + threadIdx.y + i;
        float v = tile[threadIdx.x][threadIdx.y + i];
        __nv_bfloat16 h = __float2bfloat16_rn(v);
        th[(size_t)nn * D_MODEL + k] = h;
        tl[(size_t)nn * D_MODEL + k] = __float2bfloat16_rn(v - __bfloat162float(h));
    }
}

// ---------------------------------------------------------------------------
// bf16x2-split GEMM (proven R7 core). SPLIT_OUT: epilogue writes bf16 hi/lo.
// ---------------------------------------------------------------------------
#define SA 40
#define MATB   (128 * SA * 2)
#define STAGEB (4 * MATB)
#define GSMEM  (2 * STAGEB)

template<bool SPLIT_OUT>
__global__ __launch_bounds__(256, 2) void gemm_mma(
    const __nv_bfloat16* __restrict__ Ah, const __nv_bfloat16* __restrict__ Al,
    const __nv_bfloat16* __restrict__ Bh, const __nv_bfloat16* __restrict__ Bl,
    const float* __restrict__ bias, float* __restrict__ Cf,
    __nv_bfloat16* __restrict__ Ch, __nv_bfloat16* __restrict__ Cl)
{
    extern __shared__ char smem[];
    const uint32_t sb = smem_u32(smem);

    const int tid  = threadIdx.x;
    const int wid  = tid >> 5, lane = tid & 31;
    const int wm   = wid & 3;
    const int wn   = wid >> 2;
    const int m0   = blockIdx.y * 128, n0 = blockIdx.x * 128;
    const int lg   = lane >> 2;
    const int lk   = (lane & 3) * 2;
    const int g8 = lane >> 3;
    const int r8 = lane & 7;

    float acc[2][8][4];
    #pragma unroll
    for (int mt = 0; mt < 2; mt++)
        #pragma unroll
        for (int nt = 0; nt < 8; nt++)
            #pragma unroll
            for (int r = 0; r < 4; r++) acc[mt][nt][r] = 0.f;

    auto load_stage = [&](int st, int k0) {
        const uint32_t s = sb + st * STAGEB;
        #pragma unroll
        for (int i = 0; i < 2; i++) {
            int idx = tid + i * 256;
            int r   = idx >> 2;
            int c16 = idx & 3;
            uint32_t so = (uint32_t)(r * (SA * 2) + c16 * 16);
            size_t ga = (size_t)(m0 + r) * D_MODEL + k0 + c16 * 8;
            size_t gb = (size_t)(n0 + r) * D_MODEL + k0 + c16 * 8;
            CPASYNC16(s + 0 * MATB + so, Ah + ga);
            CPASYNC16(s + 1 * MATB + so, Al + ga);
            CPASYNC16(s + 2 * MATB + so, Bh + gb);
            CPASYNC16(s + 3 * MATB + so, Bl + gb);
        }
    };

    load_stage(0, 0);
    CPCOMMIT();

    const int NIT = D_MODEL / 32;
    for (int it = 0; it < NIT; it++) {
        if (it + 1 < NIT) {
            load_stage((it + 1) & 1, (it + 1) * 32);
            CPCOMMIT();
            CPWAIT(1);
        } else {
            CPWAIT(0);
        }
        __syncthreads();

        const uint32_t s   = sb + (it & 1) * STAGEB;
        const uint32_t sAh = s;
        const uint32_t sAl = s + MATB;
        const uint32_t sBh = s + 2 * MATB;
        const uint32_t sBl = s + 3 * MATB;

        #pragma unroll
        for (int kk = 0; kk < 32; kk += 16) {
            uint32_t ah[2][4], al[2][4];
            #pragma unroll
            for (int mt = 0; mt < 2; mt++) {
                int row = wm * 32 + mt * 16 + (g8 & 1) * 8 + r8;
                int col = kk + (g8 >> 1) * 8;
                uint32_t off = (uint32_t)(row * (SA * 2) + col * 2);
                LDMX4(ah[mt][0], ah[mt][1], ah[mt][2], ah[mt][3], sAh + off);
                LDMX4(al[mt][0], al[mt][1], al[mt][2], al[mt][3], sAl + off);
            }
            #pragma unroll
            for (int np = 0; np < 4; np++) {
                int row = wn * 64 + np * 16 + (g8 >> 1) * 8 + r8;
                int col = kk + (g8 & 1) * 8;
                uint32_t off = (uint32_t)(row * (SA * 2) + col * 2);
                uint32_t bh0, bh1, bh2, bh3, bl0, bl1, bl2, bl3;
                LDMX4(bh0, bh1, bh2, bh3, sBh + off);
                LDMX4(bl0, bl1, bl2, bl3, sBl + off);
                #pragma unroll
                for (int mt = 0; mt < 2; mt++) {
                    mma16816(acc[mt][2 * np],     ah[mt], bh0, bh1);
                    mma16816(acc[mt][2 * np],     ah[mt], bl0, bl1);
                    mma16816(acc[mt][2 * np],     al[mt], bh0, bh1);
                    mma16816(acc[mt][2 * np + 1], ah[mt], bh2, bh3);
                    mma16816(acc[mt][2 * np + 1], ah[mt], bl2, bl3);
                    mma16816(acc[mt][2 * np + 1], al[mt], bh2, bh3);
                }
            }
        }
        __syncthreads();
    }

    #pragma unroll
    for (int mt = 0; mt < 2; mt++) {
        #pragma unroll
        for (int nt = 0; nt < 8; nt++) {
            int row = m0 + wm * 32 + mt * 16 + lg;
            int col = n0 + wn * 64 + nt * 8 + lk;
            float2 bb = *(const float2*)&bias[col];
            float v00 = acc[mt][nt][0] + bb.x, v01 = acc[mt][nt][1] + bb.y;
            float v10 = acc[mt][nt][2] + bb.x, v11 = acc[mt][nt][3] + bb.y;
            if (SPLIT_OUT) {
                __nv_bfloat162 h0 = __floats2bfloat162_rn(v00, v01);
                __nv_bfloat162 l0 = __floats2bfloat162_rn(
                    v00 - __bfloat162float(h0.x), v01 - __bfloat162float(h0.y));
                __nv_bfloat162 h1 = __floats2bfloat162_rn(v10, v11);
                __nv_bfloat162 l1 = __floats2bfloat162_rn(
                    v10 - __bfloat162float(h1.x), v11 - __bfloat162float(h1.y));
                *(__nv_bfloat162*)&Ch[(size_t)row * D_MODEL + col] = h0;
                *(__nv_bfloat162*)&Cl[(size_t)row * D_MODEL + col] = l0;
                *(__nv_bfloat162*)&Ch[(size_t)(row + 8) * D_MODEL + col] = h1;
                *(__nv_bfloat162*)&Cl[(size_t)(row + 8) * D_MODEL + col] = l1;
            } else {
                float2 o0 = {v00, v01}, o1 = {v10, v11};
                *(float2*)&Cf[(size_t)row * D_MODEL + col] = o0;
                *(float2*)&Cf[(size_t)(row + 8) * D_MODEL + col] = o1;
            }
        }
    }
}

// ---------------------------------------------------------------------------
// Flash-attention via mma.sync bf16 split precision (causal, UNSCALED).
// CTA: 128 q-rows of one (b,h); 8 warps x 16 rows; key tiles of 64.
// ---------------------------------------------------------------------------
#define SK   72                        // smem row stride in bf16 (144 B)
#define SKB  (SK * 2)                  // 144
#define AQ_BYTES (128 * SKB)           // 18432 per Q matrix
#define AKV_MAT  (64 * SKB)            // 9216 per K/V matrix
#define AKV_STAGE (4 * AKV_MAT)        // 36864
#define ASMEM (2 * AQ_BYTES + 2 * AKV_STAGE)   // 110592

__global__ __launch_bounds__(256, 1) void attn_mma(
    const __nv_bfloat16* __restrict__ Qh, const __nv_bfloat16* __restrict__ Ql,
    const __nv_bfloat16* __restrict__ Kh, const __nv_bfloat16* __restrict__ Kl,
    const __nv_bfloat16* __restrict__ Vh, const __nv_bfloat16* __restrict__ Vl,
    __nv_bfloat16* __restrict__ AOh, __nv_bfloat16* __restrict__ AOl)
{
    extern __shared__ char smem[];
    const uint32_t sb = smem_u32(smem);
    const uint32_t sQh = sb, sQl = sb + AQ_BYTES;
    const uint32_t sKV = sb + 2 * AQ_BYTES;

    const int qt = (gridDim.x - 1) - blockIdx.x;   // long CTAs first
    const int h  = blockIdx.y;
    const int b  = blockIdx.z;
    const int tid = threadIdx.x;
    const int wid = tid >> 5, lane = tid & 31;
    const int lg = lane >> 2, lk = (lane & 3) * 2;
    const int g8 = lane >> 3, r8 = lane & 7;

    const int q0 = qt * 128;
    const size_t gbase = ((size_t)b * SEQ) * D_MODEL + h * DEPTH;

    // ---- issue Q loads (hi+lo) ----
    #pragma unroll
    for (int i = 0; i < 4; i++) {
        int idx = tid + i * 256;             // 0..1023
        int r = idx >> 3, c = idx & 7;
        uint32_t so = (uint32_t)(r * SKB + c * 16);
        size_t g = gbase + (size_t)(q0 + r) * D_MODEL + c * 8;
        CPASYNC16(sQh + so, Qh + g);
        CPASYNC16(sQl + so, Ql + g);
    }

    auto load_kv = [&](int st, int kt) {
        const uint32_t s = sKV + st * AKV_STAGE;
        const int k0 = kt * 64;
        #pragma unroll
        for (int i = 0; i < 8; i++) {
            int idx = tid + i * 256;         // 0..2047
            int arr = idx >> 9;              // 0..3
            int r = (idx >> 3) & 63, c = idx & 7;
            uint32_t so = s + arr * AKV_MAT + (uint32_t)(r * SKB + c * 16);
            size_t g = gbase + (size_t)(k0 + r) * D_MODEL + c * 8;
            const __nv_bfloat16* src = (arr == 0) ? Kh : (arr == 1) ? Kl
                                      : (arr == 2) ? Vh : Vl;
            CPASYNC16(so, src + g);
        }
    };

    load_kv(0, 0);
    CPCOMMIT();

    float m[2] = {-1e30f, -1e30f}, l[2] = {0.f, 0.f};
    float oacc[8][4];
    #pragma unroll
    for (int nt = 0; nt < 8; nt++)
        #pragma unroll
        for (int r = 0; r < 4; r++) oacc[nt][r] = 0.f;

    uint32_t qfh[4][4], qfl[4][4];
    bool qloaded = false;

    const int last = 2 * qt + 1;
    for (int kt = 0; kt <= last; kt++) {
        if (kt < last) {
            load_kv((kt + 1) & 1, kt + 1);
            CPCOMMIT();
            CPWAIT(1);
        } else {
            CPWAIT(0);
        }
        __syncthreads();

        if (!qloaded) {   // Q frags once (register-resident)
            qloaded = true;
            #pragma unroll
            for (int ks = 0; ks < 4; ks++) {
                uint32_t off = (uint32_t)((wid * 16 + (g8 & 1) * 8 + r8) * SKB
                                          + (ks * 16 + (g8 >> 1) * 8) * 2);
                LDMX4(qfh[ks][0], qfh[ks][1], qfh[ks][2], qfh[ks][3], sQh + off);
                LDMX4(qfl[ks][0], qfl[ks][1], qfl[ks][2], qfl[ks][3], sQl + off);
            }
        }

        const uint32_t s = sKV + (kt & 1) * AKV_STAGE;
        const uint32_t sKh = s, sKl = s + AKV_MAT;
        const uint32_t sVh = s + 2 * AKV_MAT, sVl = s + 3 * AKV_MAT;

        // ---- S = Q @ K^T (split) ----
        float sacc[8][4];
        #pragma unroll
        for (int nt = 0; nt < 8; nt++)
            #pragma unroll
            for (int r = 0; r < 4; r++) sacc[nt][r] = 0.f;

        #pragma unroll
        for (int ks = 0; ks < 4; ks++) {
            #pragma unroll
            for (int np = 0; np < 4; np++) {
                uint32_t off = (uint32_t)((np * 16 + (g8 >> 1) * 8 + r8) * SKB
                                          + (ks * 16 + (g8 & 1) * 8) * 2);
                uint32_t kh0, kh1, kh2, kh3, kl0, kl1, kl2, kl3;
                LDMX4(kh0, kh1, kh2, kh3, sKh + off);
                LDMX4(kl0, kl1, kl2, kl3, sKl + off);
                mma16816(sacc[2 * np],     qfh[ks], kh0, kh1);
                mma16816(sacc[2 * np],     qfh[ks], kl0, kl1);
                mma16816(sacc[2 * np],     qfl[ks], kh0, kh1);
                mma16816(sacc[2 * np + 1], qfh[ks], kh2, kh3);
                mma16816(sacc[2 * np + 1], qfh[ks], kl2, kl3);
                mma16816(sacc[2 * np + 1], qfl[ks], kh2, kh3);
            }
        }

        // ---- causal mask (last two tiles only) ----
        if (kt >= 2 * qt) {
            const int r0 = q0 + wid * 16 + lg;
            const int kb = kt * 64;
            #pragma unroll
            for (int nt = 0; nt < 8; nt++) {
                int j0 = kb + nt * 8 + lk, j1 = j0 + 1;
                if (j0 > r0)     sacc[nt][0] = -1e30f;
                if (j1 > r0)     sacc[nt][1] = -1e30f;
                if (j0 > r0 + 8) sacc[nt][2] = -1e30f;
                if (j1 > r0 + 8) sacc[nt][3] = -1e30f;
            }
        }

        // ---- online softmax (rows lg / lg+8; 4-lane row groups) ----
        float corr[2];
        #pragma unroll
        for (int hrow = 0; hrow < 2; hrow++) {
            float rm = -1e30f;
            #pragma unroll
            for (int nt = 0; nt < 8; nt++)
                rm = fmaxf(rm, fmaxf(sacc[nt][2 * hrow], sacc[nt][2 * hrow + 1]));
            rm = fmaxf(rm, __shfl_xor_sync(0xffffffffu, rm, 1));
            rm = fmaxf(rm, __shfl_xor_sync(0xffffffffu, rm, 2));
            float mn = fmaxf(m[hrow], rm);
            corr[hrow] = __expf(m[hrow] - mn);
            m[hrow] = mn;
            float rs = 0.f;
            #pragma unroll
            for (int nt = 0; nt < 8; nt++) {
                float p0 = __expf(sacc[nt][2 * hrow]     - mn);
                float p1 = __expf(sacc[nt][2 * hrow + 1] - mn);
                sacc[nt][2 * hrow] = p0; sacc[nt][2 * hrow + 1] = p1;
                rs += p0 + p1;
            }
            rs += __shfl_xor_sync(0xffffffffu, rs, 1);
            rs += __shfl_xor_sync(0xffffffffu, rs, 2);
            l[hrow] = l[hrow] * corr[hrow] + rs;
        }
        #pragma unroll
        for (int nt = 0; nt < 8; nt++) {
            oacc[nt][0] *= corr[0]; oacc[nt][1] *= corr[0];
            oacc[nt][2] *= corr[1]; oacc[nt][3] *= corr[1];
        }

        // ---- O += P @ V (split; P built in-register from sacc) ----
        #pragma unroll
        for (int ks2 = 0; ks2 < 4; ks2++) {
            uint32_t pah[4], pal[4];
            #pragma unroll
            for (int half = 0; half < 2; half++) {     // n-tile 2ks2+half
                const float* c = sacc[2 * ks2 + half];
                __nv_bfloat162 h0 = __floats2bfloat162_rn(c[0], c[1]);
                __nv_bfloat162 h1 = __floats2bfloat162_rn(c[2], c[3]);
                pah[2 * half]     = *(uint32_t*)&h0;
                pah[2 * half + 1] = *(uint32_t*)&h1;
                __nv_bfloat162 l0 = __floats2bfloat162_rn(
                    c[0] - __bfloat162float(h0.x), c[1] - __bfloat162float(h0.y));
                __nv_bfloat162 l1 = __floats2bfloat162_rn(
                    c[2] - __bfloat162float(h1.x), c[3] - __bfloat162float(h1.y));
                pal[2 * half]     = *(uint32_t*)&l0;
                pal[2 * half + 1] = *(uint32_t*)&l1;
            }
            #pragma unroll
            for (int nd = 0; nd < 4; nd++) {
                uint32_t off = (uint32_t)((ks2 * 16 + (g8 & 1) * 8 + r8) * SKB
                                          + (nd * 16 + (g8 >> 1) * 8) * 2);
                uint32_t vh0, vh1, vh2, vh3, vl0, vl1, vl2, vl3;
                LDMX4T(vh0, vh1, vh2, vh3, sVh + off);
                LDMX4T(vl0, vl1, vl2, vl3, sVl + off);
                mma16816(oacc[2 * nd],     pah, vh0, vh1);
                mma16816(oacc[2 * nd],     pah, vl0, vl1);
                mma16816(oacc[2 * nd],     pal, vh0, vh1);
                mma16816(oacc[2 * nd + 1], pah, vh2, vh3);
                mma16816(oacc[2 * nd + 1], pah, vl2, vl3);
                mma16816(oacc[2 * nd + 1], pal, vh2, vh3);
            }
        }
        __syncthreads();
    }

    // ---- epilogue: normalize, split to bf16 hi/lo, write AO ----
    const float inv0 = 1.f / l[0], inv1 = 1.f / l[1];
    const int row0 = q0 + wid * 16 + lg;
    #pragma unroll
    for (int nt = 0; nt < 8; nt++) {
        int col = nt * 8 + lk;
        float v0 = oacc[nt][0] * inv0, v1 = oacc[nt][1] * inv0;
        __nv_bfloat162 h0 = __floats2bfloat162_rn(v0, v1);
        __nv_bfloat162 l0 = __floats2bfloat162_rn(
            v0 - __bfloat162float(h0.x), v1 - __bfloat162float(h0.y));
        *(__nv_bfloat162*)&AOh[gbase + (size_t)row0 * D_MODEL + col] = h0;
        *(__nv_bfloat162*)&AOl[gbase + (size_t)row0 * D_MODEL + col] = l0;
        float v2 = oacc[nt][2] * inv1, v3 = oacc[nt][3] * inv1;
        __nv_bfloat162 h1 = __floats2bfloat162_rn(v2, v3);
        __nv_bfloat162 l1 = __floats2bfloat162_rn(
            v2 - __bfloat162float(h1.x), v3 - __bfloat162float(h1.y));
        *(__nv_bfloat162*)&AOh[gbase + (size_t)(row0 + 8) * D_MODEL + col] = h1;
        *(__nv_bfloat162*)&AOl[gbase + (size_t)(row0 + 8) * D_MODEL + col] = l1;
    }
}

// ---------------------------------------------------------------------------
// Launch
// ---------------------------------------------------------------------------
extern "C" void kernel_launch(void* const* d_in, const int* in_sizes, int n_in,
                              void* d_out, int out_size)
{
    const float* q  = (const float*)d_in[0];
    const float* k  = (const float*)d_in[1];
    const float* v  = (const float*)d_in[2];
    const float* wq = (const float*)d_in[3];
    const float* bq = (const float*)d_in[4];
    const float* wk = (const float*)d_in[5];
    const float* bk = (const float*)d_in[6];
    const float* wv = (const float*)d_in[7];
    const float* bv = (const float*)d_in[8];
    const float* wo = (const float*)d_in[9];
    const float* bo = (const float*)d_in[10];
    float* out = (float*)d_out;

    __nv_bfloat16 *Qh, *Ql, *Kh, *Kl, *Vh, *Vl, *AOh, *AOl, *inh, *inl, *wh, *wl;
    cudaGetSymbolAddress((void**)&Qh,  g_Qh);  cudaGetSymbolAddress((void**)&Ql,  g_Ql);
    cudaGetSymbolAddress((void**)&Kh,  g_Kh);  cudaGetSymbolAddress((void**)&Kl,  g_Kl);
    cudaGetSymbolAddress((void**)&Vh,  g_Vh);  cudaGetSymbolAddress((void**)&Vl,  g_Vl);
    cudaGetSymbolAddress((void**)&AOh, g_AOh); cudaGetSymbolAddress((void**)&AOl, g_AOl);
    cudaGetSymbolAddress((void**)&inh, g_inh); cudaGetSymbolAddress((void**)&inl, g_inl);
    cudaGetSymbolAddress((void**)&wh,  g_wh);  cudaGetSymbolAddress((void**)&wl,  g_wl);

    cudaFuncSetAttribute(gemm_mma<true>,
                         cudaFuncAttributeMaxDynamicSharedMemorySize, GSMEM);
    cudaFuncSetAttribute(gemm_mma<false>,
                         cudaFuncAttributeMaxDynamicSharedMemorySize, GSMEM);
    cudaFuncSetAttribute(attn_mma,
                         cudaFuncAttributeMaxDynamicSharedMemorySize, ASMEM);

    const int nElems = ROWS * D_MODEL;
    dim3 sgrid(nElems / 4 / 256);
    dim3 tgrid(D_MODEL / 32, D_MODEL / 32), tblk(32, 8);
    dim3 ggrid(D_MODEL / 128, ROWS / 128);

    // Q projection
    split_t_kernel<<<tgrid, tblk>>>(wq, wh, wl);
    split_kernel<<<sgrid, 256>>>(q, inh, inl, nElems);
    gemm_mma<true><<<ggrid, 256, GSMEM>>>(inh, inl, wh, wl, bq, nullptr, Qh, Ql);
    // K projection
    split_t_kernel<<<tgrid, tblk>>>(wk, wh, wl);
    split_kernel<<<sgrid, 256>>>(k, inh, inl, nElems);
    gemm_mma<true><<<ggrid, 256, GSMEM>>>(inh, inl, wh, wl, bk, nullptr, Kh, Kl);
    // V projection
    split_t_kernel<<<tgrid, tblk>>>(wv, wh, wl);
    split_kernel<<<sgrid, 256>>>(v, inh, inl, nElems);
    gemm_mma<true><<<ggrid, 256, GSMEM>>>(inh, inl, wh, wl, bv, nullptr, Vh, Vl);

    // attention (mma.sync, bf16 split)
    dim3 agrid(SEQ / 128, N_HEADS, BATCH);   // (16, 16, 2)
    attn_mma<<<agrid, 256, ASMEM>>>(Qh, Ql, Kh, Kl, Vh, Vl, AOh, AOl);

    // output projection (fp32 out)
    split_t_kernel<<<tgrid, tblk>>>(wo, wh, wl);
    gemm_mma<false><<<ggrid, 256, GSMEM>>>(AOh, AOl, wh, wl, bo, out, nullptr, nullptr);
}

// round 11
// speedup vs baseline: 3.3048x; 1.0350x over previous
#include <cuda_runtime.h>
#include <cuda_bf16.h>
#include <cstdint>

#define D_MODEL 1024
#define N_HEADS 16
#define DEPTH   64
#define BATCH   2
#define SEQ     2048
#define ROWS    (BATCH*SEQ)
#define NELEMS  (ROWS*D_MODEL)
#define DD      (D_MODEL*D_MODEL)

// ---------------- scratch (device globals; no allocations) ----------------
__device__ __nv_bfloat16 g_sph [3 * NELEMS];   // split inputs (q,k,v) hi
__device__ __nv_bfloat16 g_spl [3 * NELEMS];   // split inputs lo
__device__ __nv_bfloat16 g_wh  [4 * DD];       // weights^T hi (wq,wk,wv,wo)
__device__ __nv_bfloat16 g_wl  [4 * DD];       // weights^T lo
__device__ __nv_bfloat16 g_qkvh[3 * NELEMS];   // projected Q,K,V hi
__device__ __nv_bfloat16 g_qkvl[3 * NELEMS];   // projected Q,K,V lo
__device__ __nv_bfloat16 g_aoh [NELEMS];       // attention out hi
__device__ __nv_bfloat16 g_aol [NELEMS];       // attention out lo

// ---------------- helpers ----------------
__device__ __forceinline__ uint32_t smem_u32(const void* p) {
    uint32_t a;
    asm("{ .reg .u64 t; cvta.to.shared.u64 t, %1; cvt.u32.u64 %0, t; }"
        : "=r"(a) : "l"(p));
    return a;
}
__device__ __forceinline__ void mma16816(float* d, const uint32_t* a,
                                         uint32_t b0, uint32_t b1) {
    asm volatile(
        "mma.sync.aligned.m16n8k16.row.col.f32.bf16.bf16.f32 "
        "{%0,%1,%2,%3}, {%4,%5,%6,%7}, {%8,%9}, {%0,%1,%2,%3};"
        : "+f"(d[0]), "+f"(d[1]), "+f"(d[2]), "+f"(d[3])
        : "r"(a[0]), "r"(a[1]), "r"(a[2]), "r"(a[3]), "r"(b0), "r"(b1));
}
#define LDMX4(r0, r1, r2, r3, addr) \
    asm volatile("ldmatrix.sync.aligned.m8n8.x4.shared.b16 {%0,%1,%2,%3}, [%4];" \
                 : "=r"(r0), "=r"(r1), "=r"(r2), "=r"(r3) : "r"(addr))
#define LDMX4T(r0, r1, r2, r3, addr) \
    asm volatile("ldmatrix.sync.aligned.m8n8.x4.trans.shared.b16 {%0,%1,%2,%3}, [%4];" \
                 : "=r"(r0), "=r"(r1), "=r"(r2), "=r"(r3) : "r"(addr))
#define CPASYNC16(smaddr, gptr) \
    asm volatile("cp.async.cg.shared.global [%0], [%1], 16;" \
                 :: "r"(smaddr), "l"(gptr) : "memory")
#define CPCOMMIT()  asm volatile("cp.async.commit_group;" ::: "memory")
#define CPWAIT(n)   asm volatile("cp.async.wait_group %0;" :: "n"(n) : "memory")

// ---------------------------------------------------------------------------
// Batched split: fp32 -> (bf16 hi, bf16 lo).  blockIdx.y selects input 0..2.
// ---------------------------------------------------------------------------
__global__ __launch_bounds__(256) void split3_kernel(
    const float* __restrict__ in0, const float* __restrict__ in1,
    const float* __restrict__ in2,
    __nv_bfloat16* __restrict__ hi, __nv_bfloat16* __restrict__ lo)
{
    const int z = blockIdx.y;
    const float* in = (z == 0) ? in0 : (z == 1) ? in1 : in2;
    int i = (blockIdx.x * 256 + threadIdx.x) * 4;
    if (i >= NELEMS) return;
    float4 v = *(const float4*)(in + i);
    union { __nv_bfloat16 b[4]; uint2 u; } H, L;
    float f[4] = {v.x, v.y, v.z, v.w};
    #pragma unroll
    for (int j = 0; j < 4; j++) {
        H.b[j] = __float2bfloat16_rn(f[j]);
        L.b[j] = __float2bfloat16_rn(f[j] - __bfloat162float(H.b[j]));
    }
    size_t o = (size_t)z * NELEMS + i;
    *(uint2*)(hi + o) = H.u;
    *(uint2*)(lo + o) = L.u;
}

// ---------------------------------------------------------------------------
// Batched transpose+split: W[K][N] fp32 -> Wt hi/lo [N][K] bf16. z = 0..3.
// ---------------------------------------------------------------------------
__global__ __launch_bounds__(256) void split_t4_kernel(
    const float* __restrict__ W0, const float* __restrict__ W1,
    const float* __restrict__ W2, const float* __restrict__ W3,
    __nv_bfloat16* __restrict__ th, __nv_bfloat16* __restrict__ tl)
{
    __shared__ float tile[32][33];
    const int z = blockIdx.z;
    const float* W = (z == 0) ? W0 : (z == 1) ? W1 : (z == 2) ? W2 : W3;
    const size_t zoff = (size_t)z * DD;
    int x  = blockIdx.x * 32 + threadIdx.x;
    int y0 = blockIdx.y * 32;
    #pragma unroll
    for (int i = 0; i < 32; i += 8)
        tile[threadIdx.y + i][threadIdx.x] = W[(size_t)(y0 + threadIdx.y + i) * D_MODEL + x];
    __syncthreads();
    int k = y0 + threadIdx.x;
    #pragma unroll
    for (int i = 0; i < 32; i += 8) {
        int nn = blockIdx.x * 32 + threadIdx.y + i;
        float v = tile[threadIdx.x][threadIdx.y + i];
        __nv_bfloat16 h = __float2bfloat16_rn(v);
        th[zoff + (size_t)nn * D_MODEL + k] = h;
        tl[zoff + (size_t)nn * D_MODEL + k] = __float2bfloat16_rn(v - __bfloat162float(h));
    }
}

// ---------------------------------------------------------------------------
// bf16x2-split GEMM (proven core), batched over blockIdx.z.
//   z selects A slab (z*NELEMS), weight slab (z*DD), bias, C slab.
// ---------------------------------------------------------------------------
#define SA 40
#define MATB   (128 * SA * 2)
#define STAGEB (4 * MATB)
#define GSMEM  (2 * STAGEB)

template<bool SPLIT_OUT>
__global__ __launch_bounds__(256, 2) void gemm_mma(
    const __nv_bfloat16* __restrict__ Ah0, const __nv_bfloat16* __restrict__ Al0,
    const __nv_bfloat16* __restrict__ Bh0, const __nv_bfloat16* __restrict__ Bl0,
    const float* __restrict__ b0, const float* __restrict__ b1,
    const float* __restrict__ b2,
    float* __restrict__ Cf,
    __nv_bfloat16* __restrict__ Ch0, __nv_bfloat16* __restrict__ Cl0)
{
    extern __shared__ char smem[];
    const uint32_t sb = smem_u32(smem);

    const int z = blockIdx.z;
    const __nv_bfloat16* Ah = Ah0 + (size_t)z * NELEMS;
    const __nv_bfloat16* Al = Al0 + (size_t)z * NELEMS;
    const __nv_bfloat16* Bh = Bh0 + (size_t)z * DD;
    const __nv_bfloat16* Bl = Bl0 + (size_t)z * DD;
    const float* bias = (z == 0) ? b0 : (z == 1) ? b1 : b2;
    __nv_bfloat16* Ch = Ch0 + (size_t)z * NELEMS;
    __nv_bfloat16* Cl = Cl0 + (size_t)z * NELEMS;

    const int tid  = threadIdx.x;
    const int wid  = tid >> 5, lane = tid & 31;
    const int wm   = wid & 3;
    const int wn   = wid >> 2;
    const int m0   = blockIdx.y * 128, n0 = blockIdx.x * 128;
    const int lg   = lane >> 2;
    const int lk   = (lane & 3) * 2;
    const int g8 = lane >> 3;
    const int r8 = lane & 7;

    float acc[2][8][4];
    #pragma unroll
    for (int mt = 0; mt < 2; mt++)
        #pragma unroll
        for (int nt = 0; nt < 8; nt++)
            #pragma unroll
            for (int r = 0; r < 4; r++) acc[mt][nt][r] = 0.f;

    auto load_stage = [&](int st, int k0) {
        const uint32_t s = sb + st * STAGEB;
        #pragma unroll
        for (int i = 0; i < 2; i++) {
            int idx = tid + i * 256;
            int r   = idx >> 2;
            int c16 = idx & 3;
            uint32_t so = (uint32_t)(r * (SA * 2) + c16 * 16);
            size_t ga = (size_t)(m0 + r) * D_MODEL + k0 + c16 * 8;
            size_t gb = (size_t)(n0 + r) * D_MODEL + k0 + c16 * 8;
            CPASYNC16(s + 0 * MATB + so, Ah + ga);
            CPASYNC16(s + 1 * MATB + so, Al + ga);
            CPASYNC16(s + 2 * MATB + so, Bh + gb);
            CPASYNC16(s + 3 * MATB + so, Bl + gb);
        }
    };

    load_stage(0, 0);
    CPCOMMIT();

    const int NIT = D_MODEL / 32;
    for (int it = 0; it < NIT; it++) {
        if (it + 1 < NIT) {
            load_stage((it + 1) & 1, (it + 1) * 32);
            CPCOMMIT();
            CPWAIT(1);
        } else {
            CPWAIT(0);
        }
        __syncthreads();

        const uint32_t s   = sb + (it & 1) * STAGEB;
        const uint32_t sAh = s;
        const uint32_t sAl = s + MATB;
        const uint32_t sBh = s + 2 * MATB;
        const uint32_t sBl = s + 3 * MATB;

        #pragma unroll
        for (int kk = 0; kk < 32; kk += 16) {
            uint32_t ah[2][4], al[2][4];
            #pragma unroll
            for (int mt = 0; mt < 2; mt++) {
                int row = wm * 32 + mt * 16 + (g8 & 1) * 8 + r8;
                int col = kk + (g8 >> 1) * 8;
                uint32_t off = (uint32_t)(row * (SA * 2) + col * 2);
                LDMX4(ah[mt][0], ah[mt][1], ah[mt][2], ah[mt][3], sAh + off);
                LDMX4(al[mt][0], al[mt][1], al[mt][2], al[mt][3], sAl + off);
            }
            #pragma unroll
            for (int np = 0; np < 4; np++) {
                int row = wn * 64 + np * 16 + (g8 >> 1) * 8 + r8;
                int col = kk + (g8 & 1) * 8;
                uint32_t off = (uint32_t)(row * (SA * 2) + col * 2);
                uint32_t bh0, bh1, bh2, bh3, bl0, bl1, bl2, bl3;
                LDMX4(bh0, bh1, bh2, bh3, sBh + off);
                LDMX4(bl0, bl1, bl2, bl3, sBl + off);
                #pragma unroll
                for (int mt = 0; mt < 2; mt++) {
                    mma16816(acc[mt][2 * np],     ah[mt], bh0, bh1);
                    mma16816(acc[mt][2 * np],     ah[mt], bl0, bl1);
                    mma16816(acc[mt][2 * np],     al[mt], bh0, bh1);
                    mma16816(acc[mt][2 * np + 1], ah[mt], bh2, bh3);
                    mma16816(acc[mt][2 * np + 1], ah[mt], bl2, bl3);
                    mma16816(acc[mt][2 * np + 1], al[mt], bh2, bh3);
                }
            }
        }
        __syncthreads();
    }

    #pragma unroll
    for (int mt = 0; mt < 2; mt++) {
        #pragma unroll
        for (int nt = 0; nt < 8; nt++) {
            int row = m0 + wm * 32 + mt * 16 + lg;
            int col = n0 + wn * 64 + nt * 8 + lk;
            float2 bb = *(const float2*)&bias[col];
            float v00 = acc[mt][nt][0] + bb.x, v01 = acc[mt][nt][1] + bb.y;
            float v10 = acc[mt][nt][2] + bb.x, v11 = acc[mt][nt][3] + bb.y;
            if (SPLIT_OUT) {
                __nv_bfloat162 h0 = __floats2bfloat162_rn(v00, v01);
                __nv_bfloat162 l0 = __floats2bfloat162_rn(
                    v00 - __bfloat162float(h0.x), v01 - __bfloat162float(h0.y));
                __nv_bfloat162 h1 = __floats2bfloat162_rn(v10, v11);
                __nv_bfloat162 l1 = __floats2bfloat162_rn(
                    v10 - __bfloat162float(h1.x), v11 - __bfloat162float(h1.y));
                *(__nv_bfloat162*)&Ch[(size_t)row * D_MODEL + col] = h0;
                *(__nv_bfloat162*)&Cl[(size_t)row * D_MODEL + col] = l0;
                *(__nv_bfloat162*)&Ch[(size_t)(row + 8) * D_MODEL + col] = h1;
                *(__nv_bfloat162*)&Cl[(size_t)(row + 8) * D_MODEL + col] = l1;
            } else {
                float2 o0 = {v00, v01}, o1 = {v10, v11};
                *(float2*)&Cf[(size_t)row * D_MODEL + col] = o0;
                *(float2*)&Cf[(size_t)(row + 8) * D_MODEL + col] = o1;
            }
        }
    }
}

// ---------------------------------------------------------------------------
// Flash-attention via mma.sync bf16 split precision (causal, UNSCALED).
// Q/K/V taken from the batched [3][ROWS][D_MODEL] hi/lo buffers.
// ---------------------------------------------------------------------------
#define SK   72
#define SKB  (SK * 2)
#define AQ_BYTES (128 * SKB)
#define AKV_MAT  (64 * SKB)
#define AKV_STAGE (4 * AKV_MAT)
#define ASMEM (2 * AQ_BYTES + 2 * AKV_STAGE)

__global__ __launch_bounds__(256, 1) void attn_mma(
    const __nv_bfloat16* __restrict__ qkvh, const __nv_bfloat16* __restrict__ qkvl,
    __nv_bfloat16* __restrict__ AOh, __nv_bfloat16* __restrict__ AOl)
{
    extern __shared__ char smem[];
    const uint32_t sb = smem_u32(smem);
    const uint32_t sQh = sb, sQl = sb + AQ_BYTES;
    const uint32_t sKV = sb + 2 * AQ_BYTES;

    const __nv_bfloat16* Qh = qkvh;
    const __nv_bfloat16* Ql = qkvl;
    const __nv_bfloat16* Kh = qkvh + (size_t)NELEMS;
    const __nv_bfloat16* Kl = qkvl + (size_t)NELEMS;
    const __nv_bfloat16* Vh = qkvh + 2 * (size_t)NELEMS;
    const __nv_bfloat16* Vl = qkvl + 2 * (size_t)NELEMS;

    const int qt = (gridDim.x - 1) - blockIdx.x;
    const int h  = blockIdx.y;
    const int b  = blockIdx.z;
    const int tid = threadIdx.x;
    const int wid = tid >> 5, lane = tid & 31;
    const int lg = lane >> 2, lk = (lane & 3) * 2;
    const int g8 = lane >> 3, r8 = lane & 7;

    const int q0 = qt * 128;
    const size_t gbase = ((size_t)b * SEQ) * D_MODEL + h * DEPTH;

    #pragma unroll
    for (int i = 0; i < 4; i++) {
        int idx = tid + i * 256;
        int r = idx >> 3, c = idx & 7;
        uint32_t so = (uint32_t)(r * SKB + c * 16);
        size_t g = gbase + (size_t)(q0 + r) * D_MODEL + c * 8;
        CPASYNC16(sQh + so, Qh + g);
        CPASYNC16(sQl + so, Ql + g);
    }

    auto load_kv = [&](int st, int kt) {
        const uint32_t s = sKV + st * AKV_STAGE;
        const int k0 = kt * 64;
        #pragma unroll
        for (int i = 0; i < 8; i++) {
            int idx = tid + i * 256;
            int arr = idx >> 9;
            int r = (idx >> 3) & 63, c = idx & 7;
            uint32_t so = s + arr * AKV_MAT + (uint32_t)(r * SKB + c * 16);
            size_t g = gbase + (size_t)(k0 + r) * D_MODEL + c * 8;
            const __nv_bfloat16* src = (arr == 0) ? Kh : (arr == 1) ? Kl
                                      : (arr == 2) ? Vh : Vl;
            CPASYNC16(so, src + g);
        }
    };

    load_kv(0, 0);
    CPCOMMIT();

    float m[2] = {-1e30f, -1e30f}, l[2] = {0.f, 0.f};
    float oacc[8][4];
    #pragma unroll
    for (int nt = 0; nt < 8; nt++)
        #pragma unroll
        for (int r = 0; r < 4; r++) oacc[nt][r] = 0.f;

    uint32_t qfh[4][4], qfl[4][4];
    bool qloaded = false;

    const int last = 2 * qt + 1;
    for (int kt = 0; kt <= last; kt++) {
        if (kt < last) {
            load_kv((kt + 1) & 1, kt + 1);
            CPCOMMIT();
            CPWAIT(1);
        } else {
            CPWAIT(0);
        }
        __syncthreads();

        if (!qloaded) {
            qloaded = true;
            #pragma unroll
            for (int ks = 0; ks < 4; ks++) {
                uint32_t off = (uint32_t)((wid * 16 + (g8 & 1) * 8 + r8) * SKB
                                          + (ks * 16 + (g8 >> 1) * 8) * 2);
                LDMX4(qfh[ks][0], qfh[ks][1], qfh[ks][2], qfh[ks][3], sQh + off);
                LDMX4(qfl[ks][0], qfl[ks][1], qfl[ks][2], qfl[ks][3], sQl + off);
            }
        }

        const uint32_t s = sKV + (kt & 1) * AKV_STAGE;
        const uint32_t sKh = s, sKl = s + AKV_MAT;
        const uint32_t sVh = s + 2 * AKV_MAT, sVl = s + 3 * AKV_MAT;

        float sacc[8][4];
        #pragma unroll
        for (int nt = 0; nt < 8; nt++)
            #pragma unroll
            for (int r = 0; r < 4; r++) sacc[nt][r] = 0.f;

        #pragma unroll
        for (int ks = 0; ks < 4; ks++) {
            #pragma unroll
            for (int np = 0; np < 4; np++) {
                uint32_t off = (uint32_t)((np * 16 + (g8 >> 1) * 8 + r8) * SKB
                                          + (ks * 16 + (g8 & 1) * 8) * 2);
                uint32_t kh0, kh1, kh2, kh3, kl0, kl1, kl2, kl3;
                LDMX4(kh0, kh1, kh2, kh3, sKh + off);
                LDMX4(kl0, kl1, kl2, kl3, sKl + off);
                mma16816(sacc[2 * np],     qfh[ks], kh0, kh1);
                mma16816(sacc[2 * np],     qfh[ks], kl0, kl1);
                mma16816(sacc[2 * np],     qfl[ks], kh0, kh1);
                mma16816(sacc[2 * np + 1], qfh[ks], kh2, kh3);
                mma16816(sacc[2 * np + 1], qfh[ks], kl2, kl3);
                mma16816(sacc[2 * np + 1], qfl[ks], kh2, kh3);
            }
        }

        if (kt >= 2 * qt) {
            const int r0 = q0 + wid * 16 + lg;
            const int kb = kt * 64;
            #pragma unroll
            for (int nt = 0; nt < 8; nt++) {
                int j0 = kb + nt * 8 + lk, j1 = j0 + 1;
                if (j0 > r0)     sacc[nt][0] = -1e30f;
                if (j1 > r0)     sacc[nt][1] = -1e30f;
                if (j0 > r0 + 8) sacc[nt][2] = -1e30f;
                if (j1 > r0 + 8) sacc[nt][3] = -1e30f;
            }
        }

        float corr[2];
        #pragma unroll
        for (int hrow = 0; hrow < 2; hrow++) {
            float rm = -1e30f;
            #pragma unroll
            for (int nt = 0; nt < 8; nt++)
                rm = fmaxf(rm, fmaxf(sacc[nt][2 * hrow], sacc[nt][2 * hrow + 1]));
            rm = fmaxf(rm, __shfl_xor_sync(0xffffffffu, rm, 1));
            rm = fmaxf(rm, __shfl_xor_sync(0xffffffffu, rm, 2));
            float mn = fmaxf(m[hrow], rm);
            corr[hrow] = __expf(m[hrow] - mn);
            m[hrow] = mn;
            float rs = 0.f;
            #pragma unroll
            for (int nt = 0; nt < 8; nt++) {
                float p0 = __expf(sacc[nt][2 * hrow]     - mn);
                float p1 = __expf(sacc[nt][2 * hrow + 1] - mn);
                sacc[nt][2 * hrow] = p0; sacc[nt][2 * hrow + 1] = p1;
                rs += p0 + p1;
            }
            rs += __shfl_xor_sync(0xffffffffu, rs, 1);
            rs += __shfl_xor_sync(0xffffffffu, rs, 2);
            l[hrow] = l[hrow] * corr[hrow] + rs;
        }
        #pragma unroll
        for (int nt = 0; nt < 8; nt++) {
            oacc[nt][0] *= corr[0]; oacc[nt][1] *= corr[0];
            oacc[nt][2] *= corr[1]; oacc[nt][3] *= corr[1];
        }

        #pragma unroll
        for (int ks2 = 0; ks2 < 4; ks2++) {
            uint32_t pah[4], pal[4];
            #pragma unroll
            for (int half = 0; half < 2; half++) {
                const float* c = sacc[2 * ks2 + half];
                __nv_bfloat162 h0 = __floats2bfloat162_rn(c[0], c[1]);
                __nv_bfloat162 h1 = __floats2bfloat162_rn(c[2], c[3]);
                pah[2 * half]     = *(uint32_t*)&h0;
                pah[2 * half + 1] = *(uint32_t*)&h1;
                __nv_bfloat162 l0 = __floats2bfloat162_rn(
                    c[0] - __bfloat162float(h0.x), c[1] - __bfloat162float(h0.y));
                __nv_bfloat162 l1 = __floats2bfloat162_rn(
                    c[2] - __bfloat162float(h1.x), c[3] - __bfloat162float(h1.y));
                pal[2 * half]     = *(uint32_t*)&l0;
                pal[2 * half + 1] = *(uint32_t*)&l1;
            }
            #pragma unroll
            for (int nd = 0; nd < 4; nd++) {
                uint32_t off = (uint32_t)((ks2 * 16 + (g8 & 1) * 8 + r8) * SKB
                                          + (nd * 16 + (g8 >> 1) * 8) * 2);
                uint32_t vh0, vh1, vh2, vh3, vl0, vl1, vl2, vl3;
                LDMX4T(vh0, vh1, vh2, vh3, sVh + off);
                LDMX4T(vl0, vl1, vl2, vl3, sVl + off);
                mma16816(oacc[2 * nd],     pah, vh0, vh1);
                mma16816(oacc[2 * nd],     pah, vl0, vl1);
                mma16816(oacc[2 * nd],     pal, vh0, vh1);
                mma16816(oacc[2 * nd + 1], pah, vh2, vh3);
                mma16816(oacc[2 * nd + 1], pah, vl2, vl3);
                mma16816(oacc[2 * nd + 1], pal, vh2, vh3);
            }
        }
        __syncthreads();
    }

    const float inv0 = 1.f / l[0], inv1 = 1.f / l[1];
    const int row0 = q0 + wid * 16 + lg;
    #pragma unroll
    for (int nt = 0; nt < 8; nt++) {
        int col = nt * 8 + lk;
        float v0 = oacc[nt][0] * inv0, v1 = oacc[nt][1] * inv0;
        __nv_bfloat162 h0 = __floats2bfloat162_rn(v0, v1);
        __nv_bfloat162 l0 = __floats2bfloat162_rn(
            v0 - __bfloat162float(h0.x), v1 - __bfloat162float(h0.y));
        *(__nv_bfloat162*)&AOh[gbase + (size_t)row0 * D_MODEL + col] = h0;
        *(__nv_bfloat162*)&AOl[gbase + (size_t)row0 * D_MODEL + col] = l0;
        float v2 = oacc[nt][2] * inv1, v3 = oacc[nt][3] * inv1;
        __nv_bfloat162 h1 = __floats2bfloat162_rn(v2, v3);
        __nv_bfloat162 l1 = __floats2bfloat162_rn(
            v2 - __bfloat162float(h1.x), v3 - __bfloat162float(h1.y));
        *(__nv_bfloat162*)&AOh[gbase + (size_t)(row0 + 8) * D_MODEL + col] = h1;
        *(__nv_bfloat162*)&AOl[gbase + (size_t)(row0 + 8) * D_MODEL + col] = l1;
    }
}

// ---------------------------------------------------------------------------
// Launch — 5 kernels total
// ---------------------------------------------------------------------------
extern "C" void kernel_launch(void* const* d_in, const int* in_sizes, int n_in,
                              void* d_out, int out_size)
{
    const float* q  = (const float*)d_in[0];
    const float* k  = (const float*)d_in[1];
    const float* v  = (const float*)d_in[2];
    const float* wq = (const float*)d_in[3];
    const float* bq = (const float*)d_in[4];
    const float* wk = (const float*)d_in[5];
    const float* bk = (const float*)d_in[6];
    const float* wv = (const float*)d_in[7];
    const float* bv = (const float*)d_in[8];
    const float* wo = (const float*)d_in[9];
    const float* bo = (const float*)d_in[10];
    float* out = (float*)d_out;

    __nv_bfloat16 *sph, *spl, *wh, *wl, *qkvh, *qkvl, *aoh, *aol;
    cudaGetSymbolAddress((void**)&sph,  g_sph);  cudaGetSymbolAddress((void**)&spl,  g_spl);
    cudaGetSymbolAddress((void**)&wh,   g_wh);   cudaGetSymbolAddress((void**)&wl,   g_wl);
    cudaGetSymbolAddress((void**)&qkvh, g_qkvh); cudaGetSymbolAddress((void**)&qkvl, g_qkvl);
    cudaGetSymbolAddress((void**)&aoh,  g_aoh);  cudaGetSymbolAddress((void**)&aol,  g_aol);

    cudaFuncSetAttribute(gemm_mma<true>,
                         cudaFuncAttributeMaxDynamicSharedMemorySize, GSMEM);
    cudaFuncSetAttribute(gemm_mma<false>,
                         cudaFuncAttributeMaxDynamicSharedMemorySize, GSMEM);
    cudaFuncSetAttribute(attn_mma,
                         cudaFuncAttributeMaxDynamicSharedMemorySize, ASMEM);

    // 1) transpose+split all 4 weights
    dim3 tgrid(D_MODEL / 32, D_MODEL / 32, 4), tblk(32, 8);
    split_t4_kernel<<<tgrid, tblk>>>(wq, wk, wv, wo, wh, wl);

    // 2) split q,k,v inputs
    dim3 sgrid(NELEMS / 4 / 256, 3);
    split3_kernel<<<sgrid, 256>>>(q, k, v, sph, spl);

    // 3) batched QKV projection
    dim3 ggrid(D_MODEL / 128, ROWS / 128, 3);   // (8, 32, 3)
    gemm_mma<true><<<ggrid, 256, GSMEM>>>(sph, spl, wh, wl, bq, bk, bv,
                                          nullptr, qkvh, qkvl);

    // 4) attention
    dim3 agrid(SEQ / 128, N_HEADS, BATCH);      // (16, 16, 2)
    attn_mma<<<agrid, 256, ASMEM>>>(qkvh, qkvl, aoh, aol);

    // 5) output projection (weight slab 3 = wo)
    dim3 ogrid(D_MODEL / 128, ROWS / 128, 1);
    gemm_mma<false><<<ogrid, 256, GSMEM>>>(aoh, aol, wh + 3 * (size_t)DD,
                                           wl + 3 * (size_t)DD, bo, bo, bo,
                                           out, nullptr, nullptr);
}

// round 13
// speedup vs baseline: 3.3394x; 1.0105x over previous
#include <cuda_runtime.h>
#include <cuda_bf16.h>
#include <cstdint>

#define D_MODEL 1024
#define N_HEADS 16
#define DEPTH   64
#define BATCH   2
#define SEQ     2048
#define ROWS    (BATCH*SEQ)
#define NELEMS  (ROWS*D_MODEL)
#define DD      (D_MODEL*D_MODEL)

// ---------------- scratch (device globals; no allocations) ----------------
__device__ __nv_bfloat16 g_sph [3 * NELEMS];   // split inputs (q,k,v) hi
__device__ __nv_bfloat16 g_spl [3 * NELEMS];   // split inputs lo
__device__ __nv_bfloat16 g_wh  [4 * DD];       // weights^T hi (wq,wk,wv,wo)
__device__ __nv_bfloat16 g_wl  [4 * DD];       // weights^T lo
__device__ __nv_bfloat16 g_qkvh[3 * NELEMS];   // projected Q,K,V hi
__device__ __nv_bfloat16 g_qkvl[3 * NELEMS];   // projected Q,K,V lo
__device__ __nv_bfloat16 g_aoh [NELEMS];       // attention out hi
__device__ __nv_bfloat16 g_aol [NELEMS];       // attention out lo

// ---------------- helpers ----------------
__device__ __forceinline__ uint32_t smem_u32(const void* p) {
    uint32_t a;
    asm("{ .reg .u64 t; cvta.to.shared.u64 t, %1; cvt.u32.u64 %0, t; }"
        : "=r"(a) : "l"(p));
    return a;
}
__device__ __forceinline__ void mma16816(float* d, const uint32_t* a,
                                         uint32_t b0, uint32_t b1) {
    asm volatile(
        "mma.sync.aligned.m16n8k16.row.col.f32.bf16.bf16.f32 "
        "{%0,%1,%2,%3}, {%4,%5,%6,%7}, {%8,%9}, {%0,%1,%2,%3};"
        : "+f"(d[0]), "+f"(d[1]), "+f"(d[2]), "+f"(d[3])
        : "r"(a[0]), "r"(a[1]), "r"(a[2]), "r"(a[3]), "r"(b0), "r"(b1));
}
#define LDMX4(r0, r1, r2, r3, addr) \
    asm volatile("ldmatrix.sync.aligned.m8n8.x4.shared.b16 {%0,%1,%2,%3}, [%4];" \
                 : "=r"(r0), "=r"(r1), "=r"(r2), "=r"(r3) : "r"(addr))
#define LDMX4T(r0, r1, r2, r3, addr) \
    asm volatile("ldmatrix.sync.aligned.m8n8.x4.trans.shared.b16 {%0,%1,%2,%3}, [%4];" \
                 : "=r"(r0), "=r"(r1), "=r"(r2), "=r"(r3) : "r"(addr))
#define CPASYNC16(smaddr, gptr) \
    asm volatile("cp.async.cg.shared.global [%0], [%1], 16;" \
                 :: "r"(smaddr), "l"(gptr) : "memory")
#define CPCOMMIT()  asm volatile("cp.async.commit_group;" ::: "memory")
#define CPWAIT(n)   asm volatile("cp.async.wait_group %0;" :: "n"(n) : "memory")

// ---------------------------------------------------------------------------
// Batched split: fp32 -> (bf16 hi, bf16 lo).  blockIdx.y selects input 0..2.
// ---------------------------------------------------------------------------
__global__ __launch_bounds__(256) void split3_kernel(
    const float* __restrict__ in0, const float* __restrict__ in1,
    const float* __restrict__ in2,
    __nv_bfloat16* __restrict__ hi, __nv_bfloat16* __restrict__ lo)
{
    const int z = blockIdx.y;
    const float* in = (z == 0) ? in0 : (z == 1) ? in1 : in2;
    int i = (blockIdx.x * 256 + threadIdx.x) * 4;
    if (i >= NELEMS) return;
    float4 v = *(const float4*)(in + i);
    union { __nv_bfloat16 b[4]; uint2 u; } H, L;
    float f[4] = {v.x, v.y, v.z, v.w};
    #pragma unroll
    for (int j = 0; j < 4; j++) {
        H.b[j] = __float2bfloat16_rn(f[j]);
        L.b[j] = __float2bfloat16_rn(f[j] - __bfloat162float(H.b[j]));
    }
    size_t o = (size_t)z * NELEMS + i;
    *(uint2*)(hi + o) = H.u;
    *(uint2*)(lo + o) = L.u;
}

// ---------------------------------------------------------------------------
// Batched transpose+split: W[K][N] fp32 -> Wt hi/lo [N][K] bf16. z = 0..3.
// ---------------------------------------------------------------------------
__global__ __launch_bounds__(256) void split_t4_kernel(
    const float* __restrict__ W0, const float* __restrict__ W1,
    const float* __restrict__ W2, const float* __restrict__ W3,
    __nv_bfloat16* __restrict__ th, __nv_bfloat16* __restrict__ tl)
{
    __shared__ float tile[32][33];
    const int z = blockIdx.z;
    const float* W = (z == 0) ? W0 : (z == 1) ? W1 : (z == 2) ? W2 : W3;
    const size_t zoff = (size_t)z * DD;
    int x  = blockIdx.x * 32 + threadIdx.x;
    int y0 = blockIdx.y * 32;
    #pragma unroll
    for (int i = 0; i < 32; i += 8)
        tile[threadIdx.y + i][threadIdx.x] = W[(size_t)(y0 + threadIdx.y + i) * D_MODEL + x];
    __syncthreads();
    int k = y0 + threadIdx.x;
    #pragma unroll
    for (int i = 0; i < 32; i += 8) {
        int nn = blockIdx.x * 32 + threadIdx.y + i;
        float v = tile[threadIdx.x][threadIdx.y + i];
        __nv_bfloat16 h = __float2bfloat16_rn(v);
        th[zoff + (size_t)nn * D_MODEL + k] = h;
        tl[zoff + (size_t)nn * D_MODEL + k] = __float2bfloat16_rn(v - __bfloat162float(h));
    }
}

// ---------------------------------------------------------------------------
// bf16x2-split GEMM (proven core), batched over blockIdx.z.
// ---------------------------------------------------------------------------
#define SA 40
#define MATB   (128 * SA * 2)
#define STAGEB (4 * MATB)
#define GSMEM  (2 * STAGEB)

template<bool SPLIT_OUT>
__global__ __launch_bounds__(256, 2) void gemm_mma(
    const __nv_bfloat16* __restrict__ Ah0, const __nv_bfloat16* __restrict__ Al0,
    const __nv_bfloat16* __restrict__ Bh0, const __nv_bfloat16* __restrict__ Bl0,
    const float* __restrict__ b0, const float* __restrict__ b1,
    const float* __restrict__ b2,
    float* __restrict__ Cf,
    __nv_bfloat16* __restrict__ Ch0, __nv_bfloat16* __restrict__ Cl0)
{
    extern __shared__ char smem[];
    const uint32_t sb = smem_u32(smem);

    const int z = blockIdx.z;
    const __nv_bfloat16* Ah = Ah0 + (size_t)z * NELEMS;
    const __nv_bfloat16* Al = Al0 + (size_t)z * NELEMS;
    const __nv_bfloat16* Bh = Bh0 + (size_t)z * DD;
    const __nv_bfloat16* Bl = Bl0 + (size_t)z * DD;
    const float* bias = (z == 0) ? b0 : (z == 1) ? b1 : b2;
    __nv_bfloat16* Ch = Ch0 + (size_t)z * NELEMS;
    __nv_bfloat16* Cl = Cl0 + (size_t)z * NELEMS;

    const int tid  = threadIdx.x;
    const int wid  = tid >> 5, lane = tid & 31;
    const int wm   = wid & 3;
    const int wn   = wid >> 2;
    const int m0   = blockIdx.y * 128, n0 = blockIdx.x * 128;
    const int lg   = lane >> 2;
    const int lk   = (lane & 3) * 2;
    const int g8 = lane >> 3;
    const int r8 = lane & 7;

    float acc[2][8][4];
    #pragma unroll
    for (int mt = 0; mt < 2; mt++)
        #pragma unroll
        for (int nt = 0; nt < 8; nt++)
            #pragma unroll
            for (int r = 0; r < 4; r++) acc[mt][nt][r] = 0.f;

    auto load_stage = [&](int st, int k0) {
        const uint32_t s = sb + st * STAGEB;
        #pragma unroll
        for (int i = 0; i < 2; i++) {
            int idx = tid + i * 256;
            int r   = idx >> 2;
            int c16 = idx & 3;
            uint32_t so = (uint32_t)(r * (SA * 2) + c16 * 16);
            size_t ga = (size_t)(m0 + r) * D_MODEL + k0 + c16 * 8;
            size_t gb = (size_t)(n0 + r) * D_MODEL + k0 + c16 * 8;
            CPASYNC16(s + 0 * MATB + so, Ah + ga);
            CPASYNC16(s + 1 * MATB + so, Al + ga);
            CPASYNC16(s + 2 * MATB + so, Bh + gb);
            CPASYNC16(s + 3 * MATB + so, Bl + gb);
        }
    };

    load_stage(0, 0);
    CPCOMMIT();

    const int NIT = D_MODEL / 32;
    for (int it = 0; it < NIT; it++) {
        if (it + 1 < NIT) {
            load_stage((it + 1) & 1, (it + 1) * 32);
            CPCOMMIT();
            CPWAIT(1);
        } else {
            CPWAIT(0);
        }
        __syncthreads();

        const uint32_t s   = sb + (it & 1) * STAGEB;
        const uint32_t sAh = s;
        const uint32_t sAl = s + MATB;
        const uint32_t sBh = s + 2 * MATB;
        const uint32_t sBl = s + 3 * MATB;

        #pragma unroll
        for (int kk = 0; kk < 32; kk += 16) {
            uint32_t ah[2][4], al[2][4];
            #pragma unroll
            for (int mt = 0; mt < 2; mt++) {
                int row = wm * 32 + mt * 16 + (g8 & 1) * 8 + r8;
                int col = kk + (g8 >> 1) * 8;
                uint32_t off = (uint32_t)(row * (SA * 2) + col * 2);
                LDMX4(ah[mt][0], ah[mt][1], ah[mt][2], ah[mt][3], sAh + off);
                LDMX4(al[mt][0], al[mt][1], al[mt][2], al[mt][3], sAl + off);
            }
            #pragma unroll
            for (int np = 0; np < 4; np++) {
                int row = wn * 64 + np * 16 + (g8 >> 1) * 8 + r8;
                int col = kk + (g8 & 1) * 8;
                uint32_t off = (uint32_t)(row * (SA * 2) + col * 2);
                uint32_t bh0, bh1, bh2, bh3, bl0, bl1, bl2, bl3;
                LDMX4(bh0, bh1, bh2, bh3, sBh + off);
                LDMX4(bl0, bl1, bl2, bl3, sBl + off);
                #pragma unroll
                for (int mt = 0; mt < 2; mt++) {
                    mma16816(acc[mt][2 * np],     ah[mt], bh0, bh1);
                    mma16816(acc[mt][2 * np],     ah[mt], bl0, bl1);
                    mma16816(acc[mt][2 * np],     al[mt], bh0, bh1);
                    mma16816(acc[mt][2 * np + 1], ah[mt], bh2, bh3);
                    mma16816(acc[mt][2 * np + 1], ah[mt], bl2, bl3);
                    mma16816(acc[mt][2 * np + 1], al[mt], bh2, bh3);
                }
            }
        }
        __syncthreads();
    }

    #pragma unroll
    for (int mt = 0; mt < 2; mt++) {
        #pragma unroll
        for (int nt = 0; nt < 8; nt++) {
            int row = m0 + wm * 32 + mt * 16 + lg;
            int col = n0 + wn * 64 + nt * 8 + lk;
            float2 bb = *(const float2*)&bias[col];
            float v00 = acc[mt][nt][0] + bb.x, v01 = acc[mt][nt][1] + bb.y;
            float v10 = acc[mt][nt][2] + bb.x, v11 = acc[mt][nt][3] + bb.y;
            if (SPLIT_OUT) {
                __nv_bfloat162 h0 = __floats2bfloat162_rn(v00, v01);
                __nv_bfloat162 l0 = __floats2bfloat162_rn(
                    v00 - __bfloat162float(h0.x), v01 - __bfloat162float(h0.y));
                __nv_bfloat162 h1 = __floats2bfloat162_rn(v10, v11);
                __nv_bfloat162 l1 = __floats2bfloat162_rn(
                    v10 - __bfloat162float(h1.x), v11 - __bfloat162float(h1.y));
                *(__nv_bfloat162*)&Ch[(size_t)row * D_MODEL + col] = h0;
                *(__nv_bfloat162*)&Cl[(size_t)row * D_MODEL + col] = l0;
                *(__nv_bfloat162*)&Ch[(size_t)(row + 8) * D_MODEL + col] = h1;
                *(__nv_bfloat162*)&Cl[(size_t)(row + 8) * D_MODEL + col] = l1;
            } else {
                float2 o0 = {v00, v01}, o1 = {v10, v11};
                *(float2*)&Cf[(size_t)row * D_MODEL + col] = o0;
                *(float2*)&Cf[(size_t)(row + 8) * D_MODEL + col] = o1;
            }
        }
    }
}

// ---------------------------------------------------------------------------
// Flash-attention via mma.sync bf16 split precision (causal, UNSCALED).
// KV pipeline stage = 128 keys (two 64-key compute halves per barrier pair).
// ---------------------------------------------------------------------------
#define SK   72
#define SKB  (SK * 2)                    // 144 B row stride
#define AQ_BYTES  (128 * SKB)            // 18432 per Q matrix
#define AKV_MAT   (128 * SKB)            // 18432 per K/V matrix (128 keys)
#define AKV_STAGE (4 * AKV_MAT)          // 73728
#define ASMEM (2 * AQ_BYTES + 2 * AKV_STAGE)   // 184320

__global__ __launch_bounds__(256, 1) void attn_mma(
    const __nv_bfloat16* __restrict__ qkvh, const __nv_bfloat16* __restrict__ qkvl,
    __nv_bfloat16* __restrict__ AOh, __nv_bfloat16* __restrict__ AOl)
{
    extern __shared__ char smem[];
    const uint32_t sb = smem_u32(smem);
    const uint32_t sQh = sb, sQl = sb + AQ_BYTES;
    const uint32_t sKV = sb + 2 * AQ_BYTES;

    const __nv_bfloat16* Qh = qkvh;
    const __nv_bfloat16* Ql = qkvl;
    const __nv_bfloat16* Kh = qkvh + (size_t)NELEMS;
    const __nv_bfloat16* Kl = qkvl + (size_t)NELEMS;
    const __nv_bfloat16* Vh = qkvh + 2 * (size_t)NELEMS;
    const __nv_bfloat16* Vl = qkvl + 2 * (size_t)NELEMS;

    const int qt = (gridDim.x - 1) - blockIdx.x;   // long CTAs first
    const int h  = blockIdx.y;
    const int b  = blockIdx.z;
    const int tid = threadIdx.x;
    const int wid = tid >> 5, lane = tid & 31;
    const int lg = lane >> 2, lk = (lane & 3) * 2;
    const int g8 = lane >> 3, r8 = lane & 7;

    const int q0 = qt * 128;
    const size_t gbase = ((size_t)b * SEQ) * D_MODEL + h * DEPTH;

    // ---- Q loads (hi+lo) ----
    #pragma unroll
    for (int i = 0; i < 4; i++) {
        int idx = tid + i * 256;
        int r = idx >> 3, c = idx & 7;
        uint32_t so = (uint32_t)(r * SKB + c * 16);
        size_t g = gbase + (size_t)(q0 + r) * D_MODEL + c * 8;
        CPASYNC16(sQh + so, Qh + g);
        CPASYNC16(sQl + so, Ql + g);
    }

    // 128-key stage loader: 4 arrays x 128 rows x 128B = 64KB
    auto load_kv = [&](int st, int t) {
        const uint32_t s = sKV + st * AKV_STAGE;
        const int k0 = t * 128;
        #pragma unroll
        for (int i = 0; i < 16; i++) {
            int idx = tid + i * 256;          // 0..4095
            int arr = idx >> 10;              // 0..3
            int r = (idx >> 3) & 127, c = idx & 7;
            uint32_t so = s + arr * AKV_MAT + (uint32_t)(r * SKB + c * 16);
            size_t g = gbase + (size_t)(k0 + r) * D_MODEL + c * 8;
            const __nv_bfloat16* src = (arr == 0) ? Kh : (arr == 1) ? Kl
                                      : (arr == 2) ? Vh : Vl;
            CPASYNC16(so, src + g);
        }
    };

    load_kv(0, 0);
    CPCOMMIT();

    float m[2] = {-1e30f, -1e30f}, l[2] = {0.f, 0.f};
    float oacc[8][4];
    #pragma unroll
    for (int nt = 0; nt < 8; nt++)
        #pragma unroll
        for (int r = 0; r < 4; r++) oacc[nt][r] = 0.f;

    uint32_t qfh[4][4], qfl[4][4];
    bool qloaded = false;

    for (int t = 0; t <= qt; t++) {
        if (t < qt) {
            load_kv((t + 1) & 1, t + 1);
            CPCOMMIT();
            CPWAIT(1);
        } else {
            CPWAIT(0);
        }
        __syncthreads();

        if (!qloaded) {   // Q frags once (register-resident)
            qloaded = true;
            #pragma unroll
            for (int ks = 0; ks < 4; ks++) {
                uint32_t off = (uint32_t)((wid * 16 + (g8 & 1) * 8 + r8) * SKB
                                          + (ks * 16 + (g8 >> 1) * 8) * 2);
                LDMX4(qfh[ks][0], qfh[ks][1], qfh[ks][2], qfh[ks][3], sQh + off);
                LDMX4(qfl[ks][0], qfl[ks][1], qfl[ks][2], qfl[ks][3], sQl + off);
            }
        }

        const uint32_t sg = sKV + (t & 1) * AKV_STAGE;

        #pragma unroll
        for (int half = 0; half < 2; half++) {
            const uint32_t hoff = (uint32_t)(half * 64 * SKB);
            const uint32_t sKh = sg + hoff;
            const uint32_t sKl = sg + AKV_MAT + hoff;
            const uint32_t sVh = sg + 2 * AKV_MAT + hoff;
            const uint32_t sVl = sg + 3 * AKV_MAT + hoff;
            const int kb = t * 128 + half * 64;

            // ---- S = Q @ K^T (split) ----
            float sacc[8][4];
            #pragma unroll
            for (int nt = 0; nt < 8; nt++)
                #pragma unroll
                for (int r = 0; r < 4; r++) sacc[nt][r] = 0.f;

            #pragma unroll
            for (int ks = 0; ks < 4; ks++) {
                #pragma unroll
                for (int np = 0; np < 4; np++) {
                    uint32_t off = (uint32_t)((np * 16 + (g8 >> 1) * 8 + r8) * SKB
                                              + (ks * 16 + (g8 & 1) * 8) * 2);
                    uint32_t kh0, kh1, kh2, kh3, kl0, kl1, kl2, kl3;
                    LDMX4(kh0, kh1, kh2, kh3, sKh + off);
                    LDMX4(kl0, kl1, kl2, kl3, sKl + off);
                    mma16816(sacc[2 * np],     qfh[ks], kh0, kh1);
                    mma16816(sacc[2 * np],     qfh[ks], kl0, kl1);
                    mma16816(sacc[2 * np],     qfl[ks], kh0, kh1);
                    mma16816(sacc[2 * np + 1], qfh[ks], kh2, kh3);
                    mma16816(sacc[2 * np + 1], qfh[ks], kl2, kl3);
                    mma16816(sacc[2 * np + 1], qfl[ks], kh2, kh3);
                }
            }

            // ---- causal mask (only diagonal 128-tile) ----
            if (t == qt) {
                const int r0 = q0 + wid * 16 + lg;
                #pragma unroll
                for (int nt = 0; nt < 8; nt++) {
                    int j0 = kb + nt * 8 + lk, j1 = j0 + 1;
                    if (j0 > r0)     sacc[nt][0] = -1e30f;
                    if (j1 > r0)     sacc[nt][1] = -1e30f;
                    if (j0 > r0 + 8) sacc[nt][2] = -1e30f;
                    if (j1 > r0 + 8) sacc[nt][3] = -1e30f;
                }
            }

            // ---- online softmax ----
            float corr[2];
            #pragma unroll
            for (int hrow = 0; hrow < 2; hrow++) {
                float rm = -1e30f;
                #pragma unroll
                for (int nt = 0; nt < 8; nt++)
                    rm = fmaxf(rm, fmaxf(sacc[nt][2 * hrow], sacc[nt][2 * hrow + 1]));
                rm = fmaxf(rm, __shfl_xor_sync(0xffffffffu, rm, 1));
                rm = fmaxf(rm, __shfl_xor_sync(0xffffffffu, rm, 2));
                float mn = fmaxf(m[hrow], rm);
                corr[hrow] = __expf(m[hrow] - mn);
                m[hrow] = mn;
                float rs = 0.f;
                #pragma unroll
                for (int nt = 0; nt < 8; nt++) {
                    float p0 = __expf(sacc[nt][2 * hrow]     - mn);
                    float p1 = __expf(sacc[nt][2 * hrow + 1] - mn);
                    sacc[nt][2 * hrow] = p0; sacc[nt][2 * hrow + 1] = p1;
                    rs += p0 + p1;
                }
                rs += __shfl_xor_sync(0xffffffffu, rs, 1);
                rs += __shfl_xor_sync(0xffffffffu, rs, 2);
                l[hrow] = l[hrow] * corr[hrow] + rs;
            }
            #pragma unroll
            for (int nt = 0; nt < 8; nt++) {
                oacc[nt][0] *= corr[0]; oacc[nt][1] *= corr[0];
                oacc[nt][2] *= corr[1]; oacc[nt][3] *= corr[1];
            }

            // ---- O += P @ V (split; P fragments built in-register) ----
            #pragma unroll
            for (int ks2 = 0; ks2 < 4; ks2++) {
                uint32_t pah[4], pal[4];
                #pragma unroll
                for (int hf = 0; hf < 2; hf++) {
                    const float* c = sacc[2 * ks2 + hf];
                    __nv_bfloat162 h0 = __floats2bfloat162_rn(c[0], c[1]);
                    __nv_bfloat162 h1 = __floats2bfloat162_rn(c[2], c[3]);
                    pah[2 * hf]     = *(uint32_t*)&h0;
                    pah[2 * hf + 1] = *(uint32_t*)&h1;
                    __nv_bfloat162 l0 = __floats2bfloat162_rn(
                        c[0] - __bfloat162float(h0.x), c[1] - __bfloat162float(h0.y));
                    __nv_bfloat162 l1 = __floats2bfloat162_rn(
                        c[2] - __bfloat162float(h1.x), c[3] - __bfloat162float(h1.y));
                    pal[2 * hf]     = *(uint32_t*)&l0;
                    pal[2 * hf + 1] = *(uint32_t*)&l1;
                }
                #pragma unroll
                for (int nd = 0; nd < 4; nd++) {
                    uint32_t off = (uint32_t)((ks2 * 16 + (g8 & 1) * 8 + r8) * SKB
                                              + (nd * 16 + (g8 >> 1) * 8) * 2);
                    uint32_t vh0, vh1, vh2, vh3, vl0, vl1, vl2, vl3;
                    LDMX4T(vh0, vh1, vh2, vh3, sVh + off);
                    LDMX4T(vl0, vl1, vl2, vl3, sVl + off);
                    mma16816(oacc[2 * nd],     pah, vh0, vh1);
                    mma16816(oacc[2 * nd],     pah, vl0, vl1);
                    mma16816(oacc[2 * nd],     pal, vh0, vh1);
                    mma16816(oacc[2 * nd + 1], pah, vh2, vh3);
                    mma16816(oacc[2 * nd + 1], pah, vl2, vl3);
                    mma16816(oacc[2 * nd + 1], pal, vh2, vh3);
                }
            }
        }
        __syncthreads();
    }

    // ---- epilogue ----
    const float inv0 = 1.f / l[0], inv1 = 1.f / l[1];
    const int row0 = q0 + wid * 16 + lg;
    #pragma unroll
    for (int nt = 0; nt < 8; nt++) {
        int col = nt * 8 + lk;
        float v0 = oacc[nt][0] * inv0, v1 = oacc[nt][1] * inv0;
        __nv_bfloat162 h0 = __floats2bfloat162_rn(v0, v1);
        __nv_bfloat162 l0 = __floats2bfloat162_rn(
            v0 - __bfloat162float(h0.x), v1 - __bfloat162float(h0.y));
        *(__nv_bfloat162*)&AOh[gbase + (size_t)row0 * D_MODEL + col] = h0;
        *(__nv_bfloat162*)&AOl[gbase + (size_t)row0 * D_MODEL + col] = l0;
        float v2 = oacc[nt][2] * inv1, v3 = oacc[nt][3] * inv1;
        __nv_bfloat162 h1 = __floats2bfloat162_rn(v2, v3);
        __nv_bfloat162 l1 = __floats2bfloat162_rn(
            v2 - __bfloat162float(h1.x), v3 - __bfloat162float(h1.y));
        *(__nv_bfloat162*)&AOh[gbase + (size_t)(row0 + 8) * D_MODEL + col] = h1;
        *(__nv_bfloat162*)&AOl[gbase + (size_t)(row0 + 8) * D_MODEL + col] = l1;
    }
}

// ---------------------------------------------------------------------------
// Launch — 5 kernels total
// ---------------------------------------------------------------------------
extern "C" void kernel_launch(void* const* d_in, const int* in_sizes, int n_in,
                              void* d_out, int out_size)
{
    const float* q  = (const float*)d_in[0];
    const float* k  = (const float*)d_in[1];
    const float* v  = (const float*)d_in[2];
    const float* wq = (const float*)d_in[3];
    const float* bq = (const float*)d_in[4];
    const float* wk = (const float*)d_in[5];
    const float* bk = (const float*)d_in[6];
    const float* wv = (const float*)d_in[7];
    const float* bv = (const float*)d_in[8];
    const float* wo = (const float*)d_in[9];
    const float* bo = (const float*)d_in[10];
    float* out = (float*)d_out;

    __nv_bfloat16 *sph, *spl, *wh, *wl, *qkvh, *qkvl, *aoh, *aol;
    cudaGetSymbolAddress((void**)&sph,  g_sph);  cudaGetSymbolAddress((void**)&spl,  g_spl);
    cudaGetSymbolAddress((void**)&wh,   g_wh);   cudaGetSymbolAddress((void**)&wl,   g_wl);
    cudaGetSymbolAddress((void**)&qkvh, g_qkvh); cudaGetSymbolAddress((void**)&qkvl, g_qkvl);
    cudaGetSymbolAddress((void**)&aoh,  g_aoh);  cudaGetSymbolAddress((void**)&aol,  g_aol);

    cudaFuncSetAttribute(gemm_mma<true>,
                         cudaFuncAttributeMaxDynamicSharedMemorySize, GSMEM);
    cudaFuncSetAttribute(gemm_mma<false>,
                         cudaFuncAttributeMaxDynamicSharedMemorySize, GSMEM);
    cudaFuncSetAttribute(attn_mma,
                         cudaFuncAttributeMaxDynamicSharedMemorySize, ASMEM);

    // 1) transpose+split all 4 weights
    dim3 tgrid(D_MODEL / 32, D_MODEL / 32, 4), tblk(32, 8);
    split_t4_kernel<<<tgrid, tblk>>>(wq, wk, wv, wo, wh, wl);

    // 2) split q,k,v inputs
    dim3 sgrid(NELEMS / 4 / 256, 3);
    split3_kernel<<<sgrid, 256>>>(q, k, v, sph, spl);

    // 3) batched QKV projection
    dim3 ggrid(D_MODEL / 128, ROWS / 128, 3);   // (8, 32, 3)
    gemm_mma<true><<<ggrid, 256, GSMEM>>>(sph, spl, wh, wl, bq, bk, bv,
                                          nullptr, qkvh, qkvl);

    // 4) attention
    dim3 agrid(SEQ / 128, N_HEADS, BATCH);      // (16, 16, 2)
    attn_mma<<<agrid, 256, ASMEM>>>(qkvh, qkvl, aoh, aol);

    // 5) output projection (weight slab 3 = wo)
    dim3 ogrid(D_MODEL / 128, ROWS / 128, 1);
    gemm_mma<false><<<ogrid, 256, GSMEM>>>(aoh, aol, wh + 3 * (size_t)DD,
                                           wl + 3 * (size_t)DD, bo, bo, bo,
                                           out, nullptr, nullptr);
}